// round 1
// baseline (speedup 1.0000x reference)
#include <cuda_runtime.h>
#include <cstdint>
#include <cstddef>

#define MAXN 50000
#define MAXE 800000
#define EPSV 1e-5f

#define FLAG_RELU 1
#define FLAG_ACC  2

// ---------------- scratch (static device globals; no allocation) ----------------
__device__ float g_stage1[MAXN * 320];
__device__ float g_p[MAXN * 64];
__device__ float g_r[MAXN * 64];
__device__ float g_agg[MAXN * 64];
__device__ float g_bufA[MAXN * 64];
__device__ float g_bufB[MAXN * 64];
__device__ float g_v[MAXN * 64];
__device__ float g_invin[MAXN];
__device__ float g_invout[MAXN];
__device__ int   g_indeg[MAXN];
__device__ int   g_outdeg[MAXN];
__device__ int   g_off[MAXN];
__device__ int   g_cursor[MAXN];
__device__ int   g_srcs[MAXE];
__device__ int   g_bsum[64];

// ---------------- graph build ----------------
__global__ void k_count(const int* __restrict__ rowv, const int* __restrict__ colv,
                        int* __restrict__ indeg, int* __restrict__ outdeg, int e) {
    int i = blockIdx.x * blockDim.x + threadIdx.x;
    if (i < e) {
        atomicAdd(&indeg[colv[i]], 1);
        atomicAdd(&outdeg[rowv[i]], 1);
    }
}

__global__ void k_scan1(const int* __restrict__ cnt, int* __restrict__ exc,
                        int* __restrict__ bsum, int n) {
    __shared__ int sh[1024];
    int t = threadIdx.x;
    int i = blockIdx.x * 1024 + t;
    int v = (i < n) ? cnt[i] : 0;
    sh[t] = v;
    __syncthreads();
    for (int d = 1; d < 1024; d <<= 1) {
        int x = (t >= d) ? sh[t - d] : 0;
        __syncthreads();
        sh[t] += x;
        __syncthreads();
    }
    if (i < n) exc[i] = sh[t] - v;          // block-local exclusive
    if (t == 1023) bsum[blockIdx.x] = sh[t]; // block total
}

__global__ void k_scan2(int* bsum, int nb) {
    if (threadIdx.x == 0 && blockIdx.x == 0) {
        int run = 0;
        for (int i = 0; i < nb; i++) { int v = bsum[i]; bsum[i] = run; run += v; }
    }
}

__global__ void k_scan3(int* __restrict__ exc, const int* __restrict__ bsum,
                        int* __restrict__ cursor, int n) {
    int i = blockIdx.x * 1024 + threadIdx.x;
    if (i < n) {
        int v = exc[i] + bsum[blockIdx.x];
        exc[i] = v;
        cursor[i] = v;
    }
}

__global__ void k_fill(const int* __restrict__ rowv, const int* __restrict__ colv,
                       int* __restrict__ cursor, int* __restrict__ srcs, int e) {
    int i = blockIdx.x * blockDim.x + threadIdx.x;
    if (i < e) {
        int c = colv[i];
        int pos = atomicAdd(&cursor[c], 1);
        srcs[pos] = rowv[i];
    }
}

__global__ void k_inv(const int* __restrict__ indeg, const int* __restrict__ outdeg,
                      float* __restrict__ invin, float* __restrict__ invout, int n) {
    int i = blockIdx.x * blockDim.x + threadIdx.x;
    if (i < n) {
        invin[i]  = 1.0f / (float)max(indeg[i], 1);
        invout[i] = 1.0f / (float)max(outdeg[i], 1);
    }
}

// ---------------- dense GEMM: C[n,64] (+)= A[n,K] @ W[K,64] ----------------
// block: 256 threads, 64 nodes, 64 cols. f32x2 packed FMA, X tile transposed.
__global__ void __launch_bounds__(256)
gemm64(const float* __restrict__ A, int lda,
       const float* __restrict__ W, int K,
       const float* __restrict__ bias,
       float* __restrict__ C, int ldc,
       int n, int flags) {
    __shared__ float Ws[64 * 64];
    __shared__ __align__(16) float Xs[64 * 66]; // [k][node], pad 66 keeps pairs 8B aligned
    int tid = threadIdx.x;
    int col = tid & 63;
    int grp = tid >> 6; // 0..3, each owns 16 nodes
    int nb = blockIdx.x * 64;

    unsigned long long acc[8];
#pragma unroll
    for (int j = 0; j < 8; j++) acc[j] = 0ull;

    for (int kc = 0; kc < K; kc += 64) {
        __syncthreads();
        for (int i = tid; i < 4096; i += 256) {
            int k = i >> 6, c = i & 63;
            Ws[k * 64 + c] = W[(size_t)(kc + k) * 64 + c];
        }
        for (int i = tid; i < 4096; i += 256) {
            int nn = i >> 6, k = i & 63;
            int node = nb + nn;
            Xs[k * 66 + nn] = (node < n) ? A[(size_t)node * lda + kc + k] : 0.0f;
        }
        __syncthreads();
#pragma unroll 8
        for (int k = 0; k < 64; k++) {
            float w = Ws[k * 64 + col];
            unsigned long long wp;
            asm("mov.b64 %0, {%1, %1};" : "=l"(wp) : "f"(w));
            const float* xrow = &Xs[k * 66 + grp * 16];
#pragma unroll
            for (int j = 0; j < 8; j++) {
                unsigned long long xv = *(const unsigned long long*)(xrow + 2 * j);
                asm("fma.rn.f32x2 %0, %1, %2, %0;" : "+l"(acc[j]) : "l"(xv), "l"(wp));
            }
        }
    }

    float b = bias ? bias[col] : 0.0f;
#pragma unroll
    for (int j = 0; j < 8; j++) {
        float lo, hi;
        asm("mov.b64 {%0, %1}, %2;" : "=f"(lo), "=f"(hi) : "l"(acc[j]));
        int n0 = nb + grp * 16 + 2 * j;
        if (n0 < n) {
            float v = lo + b;
            if (flags & FLAG_ACC) v += C[(size_t)n0 * ldc + col];
            if (flags & FLAG_RELU) v = fmaxf(v, 0.0f);
            C[(size_t)n0 * ldc + col] = v;
        }
        int n1 = n0 + 1;
        if (n1 < n) {
            float v = hi + b;
            if (flags & FLAG_ACC) v += C[(size_t)n1 * ldc + col];
            if (flags & FLAG_RELU) v = fmaxf(v, 0.0f);
            C[(size_t)n1 * ldc + col] = v;
        }
    }
}

// ---------------- CSC gather: out[n,64] = sum_{e in CSC[n]} A[src_e]* (sscale[src_e]) ----------------
__global__ void k_gather(const int* __restrict__ off, const int* __restrict__ cnt,
                         const int* __restrict__ srcs,
                         const float* __restrict__ A, int lda,
                         const float* __restrict__ sscale,
                         float* __restrict__ out, int ldo, int n) {
    int gw = (blockIdx.x * blockDim.x + threadIdx.x) >> 5;
    int lane = threadIdx.x & 31;
    if (gw >= n) return;
    int start = off[gw];
    int num = cnt[gw];
    int c2 = lane * 2;
    float ax = 0.0f, ay = 0.0f;
    int i = 0;
    int n4 = num & ~3;
    for (; i < n4; i += 4) {
        int s0 = srcs[start + i + 0];
        int s1 = srcs[start + i + 1];
        int s2 = srcs[start + i + 2];
        int s3 = srcs[start + i + 3];
        float2 v0 = *(const float2*)&A[(size_t)s0 * lda + c2];
        float2 v1 = *(const float2*)&A[(size_t)s1 * lda + c2];
        float2 v2 = *(const float2*)&A[(size_t)s2 * lda + c2];
        float2 v3 = *(const float2*)&A[(size_t)s3 * lda + c2];
        if (sscale) {
            float w0 = sscale[s0], w1 = sscale[s1], w2 = sscale[s2], w3 = sscale[s3];
            ax += v0.x * w0 + v1.x * w1 + v2.x * w2 + v3.x * w3;
            ay += v0.y * w0 + v1.y * w1 + v2.y * w2 + v3.y * w3;
        } else {
            ax += v0.x + v1.x + v2.x + v3.x;
            ay += v0.y + v1.y + v2.y + v3.y;
        }
    }
    for (; i < num; i++) {
        int s = srcs[start + i];
        float2 v = *(const float2*)&A[(size_t)s * lda + c2];
        float w = sscale ? sscale[s] : 1.0f;
        ax += v.x * w;
        ay += v.y * w;
    }
    out[(size_t)gw * ldo + c2] = ax;
    out[(size_t)gw * ldo + c2 + 1] = ay;
}

// ---------------- SAGE epilogue: relu(bn(agg*invin + bias + r)) [+ hprev] ----------------
__global__ void k_post(const float* __restrict__ agg, const float* __restrict__ invin,
                       const float* __restrict__ r, const float* __restrict__ bias,
                       const float* __restrict__ gam, const float* __restrict__ bet,
                       const float* __restrict__ mea, const float* __restrict__ var,
                       const float* __restrict__ hprev, int ldh,
                       float* __restrict__ out, int ldo, int n) {
    int idx = blockIdx.x * blockDim.x + threadIdx.x;
    if (idx >= n * 64) return;
    int node = idx >> 6, c = idx & 63;
    float val = agg[idx] * invin[node] + bias[c] + r[idx];
    val = (val - mea[c]) * rsqrtf(var[c] + EPSV) * gam[c] + bet[c];
    val = fmaxf(val, 0.0f);
    if (hprev) val += hprev[(size_t)node * ldh + c];
    out[(size_t)node * ldo + c] = val;
}

// ---------------- rank head: score = t @ W2 + b2 (t already relu'd) ----------------
__global__ void k_rankdot(const float* __restrict__ t, const float* __restrict__ W2,
                          const float* __restrict__ b2, float* __restrict__ out, int n) {
    int gw = (blockIdx.x * blockDim.x + threadIdx.x) >> 5;
    int lane = threadIdx.x & 31;
    if (gw >= n) return;
    int c = lane * 2;
    float2 tv = *(const float2*)&t[(size_t)gw * 64 + c];
    float s = tv.x * W2[c] + tv.y * W2[c + 1];
#pragma unroll
    for (int o = 16; o > 0; o >>= 1) s += __shfl_xor_sync(0xffffffffu, s, o);
    if (lane == 0) out[gw] = s + b2[0];
}

// ---------------- regressor tail: h1=relu(pre + rank*w1last + b1); h2=relu(h1@W2+b2); preds=h2@W3+b3
__global__ void k_regfinal(const float* __restrict__ pre, const float* __restrict__ w1last,
                           const float* __restrict__ b1, const float* __restrict__ score,
                           const float* __restrict__ W2, const float* __restrict__ b2,
                           const float* __restrict__ W3, const float* __restrict__ b3,
                           float* __restrict__ preds, int n) {
    __shared__ float h1s[8][66];
    int wmy = threadIdx.x >> 5;
    int lane = threadIdx.x & 31;
    int node = blockIdx.x * 8 + wmy;
    if (node >= n) return;
    float sc = score[node];
    int c = lane * 2;
    float a0 = pre[(size_t)node * 64 + c]     + sc * w1last[c]     + b1[c];
    float a1 = pre[(size_t)node * 64 + c + 1] + sc * w1last[c + 1] + b1[c + 1];
    h1s[wmy][c]     = fmaxf(a0, 0.0f);
    h1s[wmy][c + 1] = fmaxf(a1, 0.0f);
    __syncwarp();
    float h2 = b2[lane];
#pragma unroll 8
    for (int k = 0; k < 64; k++) h2 += h1s[wmy][k] * W2[k * 32 + lane];
    h2 = fmaxf(h2, 0.0f);
    float p = h2 * W3[lane];
#pragma unroll
    for (int o = 16; o > 0; o >>= 1) p += __shfl_xor_sync(0xffffffffu, p, o);
    if (lane == 0) preds[node] = p + b3[0];
}

// ---------------- host ----------------
static inline void launch_gemm64(const float* A, int lda, const float* W, int K,
                                 const float* bias, float* C, int ldc, int n, int flags) {
    gemm64<<<(n + 63) / 64, 256>>>(A, lda, W, K, bias, C, ldc, n, flags);
}

extern "C" void kernel_launch(void* const* d_in, const int* in_sizes, int n_in,
                              void* d_out, int out_size) {
    const float* x        = (const float*)d_in[0];
    const int*   ei       = (const int*)d_in[1];
    const float* W_in     = (const float*)d_in[2];
    const float* b_in     = (const float*)d_in[3];
    const float* sage_Wl  = (const float*)d_in[4];
    const float* sage_bl  = (const float*)d_in[5];
    const float* sage_Wr  = (const float*)d_in[6];
    const float* bn_g     = (const float*)d_in[7];
    const float* bn_b     = (const float*)d_in[8];
    const float* bn_m     = (const float*)d_in[9];
    const float* bn_v     = (const float*)d_in[10];
    const float* vW_l     = (const float*)d_in[11];
    const float* vb_l     = (const float*)d_in[12];
    const float* vW_r     = (const float*)d_in[13];
    const float* vbn_g    = (const float*)d_in[14];
    const float* vbn_b    = (const float*)d_in[15];
    const float* vbn_m    = (const float*)d_in[16];
    const float* vbn_v    = (const float*)d_in[17];
    const float* W_mu     = (const float*)d_in[18];
    const float* b_mu     = (const float*)d_in[19];
    const float* W_lv     = (const float*)d_in[20];
    const float* b_lv     = (const float*)d_in[21];
    const float* rank_W1  = (const float*)d_in[22];
    const float* rank_b1  = (const float*)d_in[23];
    const float* rank_W2  = (const float*)d_in[24];
    const float* rank_b2  = (const float*)d_in[25];
    const float* reg_W1   = (const float*)d_in[26];
    const float* reg_b1   = (const float*)d_in[27];
    const float* reg_W2   = (const float*)d_in[28];
    const float* reg_b2   = (const float*)d_in[29];
    const float* reg_W3   = (const float*)d_in[30];
    const float* reg_b3   = (const float*)d_in[31];

    int n = in_sizes[0] / 64;
    int e = in_sizes[1] / 2;
    const int* rowv = ei;
    const int* colv = ei + e;

    float *stage1, *p, *r, *agg, *bufA, *bufB, *vbuf, *invin, *invout;
    int *indeg, *outdeg, *off, *cursor, *srcs, *bsum;
    cudaGetSymbolAddress((void**)&stage1, g_stage1);
    cudaGetSymbolAddress((void**)&p, g_p);
    cudaGetSymbolAddress((void**)&r, g_r);
    cudaGetSymbolAddress((void**)&agg, g_agg);
    cudaGetSymbolAddress((void**)&bufA, g_bufA);
    cudaGetSymbolAddress((void**)&bufB, g_bufB);
    cudaGetSymbolAddress((void**)&vbuf, g_v);
    cudaGetSymbolAddress((void**)&invin, g_invin);
    cudaGetSymbolAddress((void**)&invout, g_invout);
    cudaGetSymbolAddress((void**)&indeg, g_indeg);
    cudaGetSymbolAddress((void**)&outdeg, g_outdeg);
    cudaGetSymbolAddress((void**)&off, g_off);
    cudaGetSymbolAddress((void**)&cursor, g_cursor);
    cudaGetSymbolAddress((void**)&srcs, g_srcs);
    cudaGetSymbolAddress((void**)&bsum, g_bsum);

    float* out_preds = (float*)d_out;
    float* out_rank  = out_preds + n;
    float* out_mu    = out_preds + 2 * (size_t)n;
    float* out_lv    = out_mu + 64 * (size_t)n;

    // ---- graph build: degrees + CSC by destination ----
    cudaMemsetAsync(indeg, 0, n * sizeof(int), 0);
    cudaMemsetAsync(outdeg, 0, n * sizeof(int), 0);
    k_count<<<(e + 255) / 256, 256>>>(rowv, colv, indeg, outdeg, e);
    int nb = (n + 1023) / 1024;
    k_scan1<<<nb, 1024>>>(indeg, off, bsum, n);
    k_scan2<<<1, 32>>>(bsum, nb);
    k_scan3<<<nb, 1024>>>(off, bsum, cursor, n);
    k_fill<<<(e + 255) / 256, 256>>>(rowv, colv, cursor, srcs, e);
    k_inv<<<(n + 255) / 256, 256>>>(indeg, outdeg, invin, invout, n);

    int gw_blocks = (n * 32 + 255) / 256;
    int ew_blocks = (n * 64 + 255) / 256;

    // ---- inp_skip -> stage1[:,256:320] ----
    launch_gemm64(x, 64, W_in, 64, b_in, stage1 + 256, 320, n, 0);

    // ---- 4 SAGE layers ----
    const float* h = x;
    int lh = 64;
    for (int i = 0; i < 4; i++) {
        launch_gemm64(h, lh, sage_Wl + (size_t)i * 4096, 64, nullptr, p, 64, n, 0);
        launch_gemm64(h, lh, sage_Wr + (size_t)i * 4096, 64, nullptr, r, 64, n, 0);
        k_gather<<<gw_blocks, 256>>>(off, indeg, srcs, p, 64, nullptr, agg, 64, n);
        k_post<<<ew_blocks, 256>>>(agg, invin, r, sage_bl + i * 64,
                                   bn_g + i * 64, bn_b + i * 64, bn_m + i * 64, bn_v + i * 64,
                                   h, lh, stage1 + i * 64, 320, n);
        h = stage1 + i * 64;
        lh = 320;
    }

    // ---- path_agg: 4 degree-normalized propagation steps ----
    k_gather<<<gw_blocks, 256>>>(off, indeg, srcs, stage1 + 192, 320, invout, bufA, 64, n);
    k_gather<<<gw_blocks, 256>>>(off, indeg, srcs, bufA, 64, invout, bufB, 64, n);
    k_gather<<<gw_blocks, 256>>>(off, indeg, srcs, bufB, 64, invout, bufA, 64, n);
    k_gather<<<gw_blocks, 256>>>(off, indeg, srcs, bufA, 64, invout, bufB, 64, n);

    // ---- VGAE sage (project-then-aggregate: mean commutes with matmul) ----
    launch_gemm64(stage1, 320, vW_l, 320, nullptr, p, 64, n, 0);
    launch_gemm64(bufB, 64, vW_l + 320 * 64, 64, nullptr, p, 64, n, FLAG_ACC);
    launch_gemm64(stage1, 320, vW_r, 320, nullptr, r, 64, n, 0);
    launch_gemm64(bufB, 64, vW_r + 320 * 64, 64, nullptr, r, 64, n, FLAG_ACC);
    k_gather<<<gw_blocks, 256>>>(off, indeg, srcs, p, 64, nullptr, agg, 64, n);
    k_post<<<ew_blocks, 256>>>(agg, invin, r, vb_l, vbn_g, vbn_b, vbn_m, vbn_v,
                               nullptr, 0, vbuf, 64, n);

    // ---- heads ----
    launch_gemm64(vbuf, 64, W_mu, 64, b_mu, out_mu, 64, n, 0);
    launch_gemm64(vbuf, 64, W_lv, 64, b_lv, out_lv, 64, n, 0);

    launch_gemm64(out_mu, 64, rank_W1, 64, rank_b1, p, 64, n, FLAG_RELU);
    k_rankdot<<<gw_blocks, 256>>>(p, rank_W2, rank_b2, out_rank, n);

    launch_gemm64(stage1, 320, reg_W1, 320, nullptr, r, 64, n, 0);
    launch_gemm64(out_mu, 64, reg_W1 + 320 * 64, 64, nullptr, r, 64, n, FLAG_ACC);
    k_regfinal<<<(n + 7) / 8, 256>>>(r, reg_W1 + 384 * 64, reg_b1, out_rank,
                                     reg_W2, reg_b2, reg_W3, reg_b3, out_preds, n);
}

// round 2
// speedup vs baseline: 1.3219x; 1.3219x over previous
#include <cuda_runtime.h>
#include <cstdint>
#include <cstddef>

#define MAXN 50000
#define MAXE 800000
#define EPSV 1e-5f

typedef unsigned long long ull;

// ---------------- scratch (static device globals; no allocation) ----------------
__device__ float g_pr[MAXN * 128];
__device__ float g_stage1[MAXN * 320];
__device__ float g_bufA[MAXN * 64];
__device__ float g_bufB[MAXN * 64];
__device__ float g_v[MAXN * 64];
__device__ float g_t[MAXN * 64];
__device__ float g_invin[MAXN];
__device__ float g_invout[MAXN];
__device__ int   g_indeg[MAXN];
__device__ int   g_outdeg[MAXN];
__device__ int   g_off[MAXN];
__device__ int   g_cursor[MAXN];
__device__ int   g_srcs[MAXE];
__device__ int   g_bsum[64];

// ---------------- graph build ----------------
__global__ void k_count(const int* __restrict__ rowv, const int* __restrict__ colv,
                        int* __restrict__ indeg, int* __restrict__ outdeg, int e) {
    int i = blockIdx.x * blockDim.x + threadIdx.x;
    if (i < e) {
        atomicAdd(&indeg[colv[i]], 1);
        atomicAdd(&outdeg[rowv[i]], 1);
    }
}

__global__ void k_scan1(const int* __restrict__ cnt, int* __restrict__ exc,
                        int* __restrict__ bsum, int n) {
    __shared__ int sh[1024];
    int t = threadIdx.x;
    int i = blockIdx.x * 1024 + t;
    int v = (i < n) ? cnt[i] : 0;
    sh[t] = v;
    __syncthreads();
    for (int d = 1; d < 1024; d <<= 1) {
        int x = (t >= d) ? sh[t - d] : 0;
        __syncthreads();
        sh[t] += x;
        __syncthreads();
    }
    if (i < n) exc[i] = sh[t] - v;
    if (t == 1023) bsum[blockIdx.x] = sh[t];
}

__global__ void k_scan2(int* bsum, int nb) {
    if (threadIdx.x == 0 && blockIdx.x == 0) {
        int run = 0;
        for (int i = 0; i < nb; i++) { int v = bsum[i]; bsum[i] = run; run += v; }
    }
}

__global__ void k_scan3(int* __restrict__ exc, const int* __restrict__ bsum,
                        int* __restrict__ cursor, int n) {
    int i = blockIdx.x * 1024 + threadIdx.x;
    if (i < n) {
        int v = exc[i] + bsum[blockIdx.x];
        exc[i] = v;
        cursor[i] = v;
    }
}

__global__ void k_fill(const int* __restrict__ rowv, const int* __restrict__ colv,
                       int* __restrict__ cursor, int* __restrict__ srcs, int e) {
    int i = blockIdx.x * blockDim.x + threadIdx.x;
    if (i < e) {
        int c = colv[i];
        int pos = atomicAdd(&cursor[c], 1);
        srcs[pos] = rowv[i];
    }
}

__global__ void k_inv(const int* __restrict__ indeg, const int* __restrict__ outdeg,
                      float* __restrict__ invin, float* __restrict__ invout, int n) {
    int i = blockIdx.x * blockDim.x + threadIdx.x;
    if (i < n) {
        invin[i]  = 1.0f / (float)max(indeg[i], 1);
        invout[i] = 1.0f / (float)max(outdeg[i], 1);
    }
}

// ---------------- dense GEMM ----------------
// C[n, NCOLS] = [A1 | A2][n, K1+K2] @ W[K1+K2, NCOLS], W split col-wise Wa|Wb.
// Tile: 64 nodes x NCOLS cols, 256 threads (8 warps). Warp owns NP=NCOLS/16
// col-pairs; lane owns node pair {2*lane, 2*lane+1}. Accumulators packed over
// column pairs -> per k: 1 LDS.64 (X pair) + 3 mov + NP LDS.64 (W broadcast) +
// 2*NP fma.f32x2. Stride-loop over tiles to avoid wave quantization.
template<int NCOLS, bool RELU>
__global__ void __launch_bounds__(256, 4)
k_gemm(const float* __restrict__ A1, int lda1, int K1,
       const float* __restrict__ A2, int lda2, int K2,
       const float* __restrict__ Wa, const float* __restrict__ Wb,
       const float* __restrict__ ba, const float* __restrict__ bb,
       float* __restrict__ C1, int ldc1, float* __restrict__ C2, int ldc2,
       int n, int ntiles)
{
    constexpr int NP = NCOLS / 16;            // col-pairs per warp
    __shared__ float Ws[64 * NCOLS];          // [k][col]
    __shared__ float2 Xs[64 * 32];            // [k][nodepair]
    const int tid = threadIdx.x;
    const int lane = tid & 31;
    const int warp = tid >> 5;
    const int Ktot = K1 + K2;

    for (int tile = blockIdx.x; tile < ntiles; tile += gridDim.x) {
        ull acc0[NP], acc1[NP];
#pragma unroll
        for (int j = 0; j < NP; j++) { acc0[j] = 0ull; acc1[j] = 0ull; }

        for (int kc = 0; kc < Ktot; kc += 64) {
            const float* A; int lda, kb;
            if (kc < K1) { A = A1; lda = lda1; kb = kc; }
            else         { A = A2; lda = lda2; kb = kc - K1; }

            __syncthreads();
            if (tid < 64) {
                // X: one thread per node, 64 k-values, transposed store (conflict-free)
                int node = tile * 64 + tid;
                const float4* src = (const float4*)(A + (size_t)node * lda + kb);
                float* xf = (float*)Xs;
#pragma unroll
                for (int q = 0; q < 16; q++) {
                    float4 v = (node < n) ? src[q] : make_float4(0.f, 0.f, 0.f, 0.f);
                    xf[(q * 4 + 0) * 64 + tid] = v.x;
                    xf[(q * 4 + 1) * 64 + tid] = v.y;
                    xf[(q * 4 + 2) * 64 + tid] = v.z;
                    xf[(q * 4 + 3) * 64 + tid] = v.w;
                }
            } else {
                const int t = tid - 64;
                for (int i = t; i < 64 * (NCOLS / 4); i += 192) {
                    int k = i / (NCOLS / 4);
                    int q4 = (i % (NCOLS / 4)) * 4;
                    const float* wsrc = (q4 < 64) ? (Wa + (size_t)(kc + k) * 64 + q4)
                                                  : (Wb + (size_t)(kc + k) * 64 + (q4 - 64));
                    *(float4*)&Ws[k * NCOLS + q4] = *(const float4*)wsrc;
                }
            }
            __syncthreads();

            const ull* xs = (const ull*)Xs + lane;
            const ull* ws = (const ull*)Ws + warp * NP;
#pragma unroll 16
            for (int k = 0; k < 64; k++) {
                ull xv = xs[k * 32];
                float x0, x1;
                asm("mov.b64 {%0,%1}, %2;" : "=f"(x0), "=f"(x1) : "l"(xv));
                ull sp0, sp1;
                asm("mov.b64 %0, {%1,%1};" : "=l"(sp0) : "f"(x0));
                asm("mov.b64 %0, {%1,%1};" : "=l"(sp1) : "f"(x1));
#pragma unroll
                for (int j = 0; j < NP; j++) {
                    ull wv = ws[k * (NCOLS / 2) + j];
                    asm("fma.rn.f32x2 %0, %1, %2, %0;" : "+l"(acc0[j]) : "l"(sp0), "l"(wv));
                    asm("fma.rn.f32x2 %0, %1, %2, %0;" : "+l"(acc1[j]) : "l"(sp1), "l"(wv));
                }
            }
        }

        // epilogue: warp's col block lives entirely in one output half
        int cb = warp * 2 * NP;
        bool half2 = (cb >= 64);
        float* C = half2 ? C2 : C1;
        int ldc = half2 ? ldc2 : ldc1;
        const float* bs = half2 ? bb : ba;
        int cofs = half2 ? cb - 64 : cb;
        int n0 = tile * 64 + 2 * lane;
#pragma unroll
        for (int j = 0; j < NP; j++) {
            float v00, v01, v10, v11;
            asm("mov.b64 {%0,%1}, %2;" : "=f"(v00), "=f"(v01) : "l"(acc0[j]));
            asm("mov.b64 {%0,%1}, %2;" : "=f"(v10), "=f"(v11) : "l"(acc1[j]));
            float b0 = bs ? bs[cofs + 2 * j] : 0.0f;
            float b1 = bs ? bs[cofs + 2 * j + 1] : 0.0f;
            v00 += b0; v01 += b1; v10 += b0; v11 += b1;
            if (RELU) {
                v00 = fmaxf(v00, 0.f); v01 = fmaxf(v01, 0.f);
                v10 = fmaxf(v10, 0.f); v11 = fmaxf(v11, 0.f);
            }
            if (n0 < n)
                *(float2*)&C[(size_t)n0 * ldc + cofs + 2 * j] = make_float2(v00, v01);
            if (n0 + 1 < n)
                *(float2*)&C[(size_t)(n0 + 1) * ldc + cofs + 2 * j] = make_float2(v10, v11);
        }
    }
}

// ---------------- CSC gather (path steps, with per-source scale) ----------------
__global__ void k_gather(const int* __restrict__ off, const int* __restrict__ cnt,
                         const int* __restrict__ srcs,
                         const float* __restrict__ A, int lda,
                         const float* __restrict__ sscale,
                         float* __restrict__ out, int ldo, int n) {
    int gw = (blockIdx.x * blockDim.x + threadIdx.x) >> 5;
    int lane = threadIdx.x & 31;
    if (gw >= n) return;
    int start = off[gw];
    int num = cnt[gw];
    int c2 = lane * 2;
    float ax = 0.0f, ay = 0.0f;
    int i = 0;
    int n4 = num & ~3;
    for (; i < n4; i += 4) {
        int s0 = srcs[start + i + 0];
        int s1 = srcs[start + i + 1];
        int s2 = srcs[start + i + 2];
        int s3 = srcs[start + i + 3];
        float2 v0 = *(const float2*)&A[(size_t)s0 * lda + c2];
        float2 v1 = *(const float2*)&A[(size_t)s1 * lda + c2];
        float2 v2 = *(const float2*)&A[(size_t)s2 * lda + c2];
        float2 v3 = *(const float2*)&A[(size_t)s3 * lda + c2];
        float w0 = sscale[s0], w1 = sscale[s1], w2 = sscale[s2], w3 = sscale[s3];
        ax += v0.x * w0 + v1.x * w1 + v2.x * w2 + v3.x * w3;
        ay += v0.y * w0 + v1.y * w1 + v2.y * w2 + v3.y * w3;
    }
    for (; i < num; i++) {
        int s = srcs[start + i];
        float2 v = *(const float2*)&A[(size_t)s * lda + c2];
        float w = sscale[s];
        ax += v.x * w;
        ay += v.y * w;
    }
    out[(size_t)gw * ldo + c2] = ax;
    out[(size_t)gw * ldo + c2 + 1] = ay;
}

// ---------------- fused gather + SAGE epilogue ----------------
// out = relu(bn(mean_agg(A) + bias + R_row)) [+ hprev_row]
__global__ void k_gatherpost(const int* __restrict__ off, const int* __restrict__ cnt,
                             const int* __restrict__ srcs,
                             const float* __restrict__ A, int lda,
                             const float* __restrict__ R, int ldr,
                             const float* __restrict__ invin,
                             const float* __restrict__ bias,
                             const float* __restrict__ gam, const float* __restrict__ bet,
                             const float* __restrict__ mea, const float* __restrict__ var,
                             const float* __restrict__ hprev, int ldh,
                             float* __restrict__ out, int ldo, int n) {
    int gw = (blockIdx.x * blockDim.x + threadIdx.x) >> 5;
    int lane = threadIdx.x & 31;
    if (gw >= n) return;
    int start = off[gw];
    int num = cnt[gw];
    int c0 = lane * 2, c1 = c0 + 1;
    float ax = 0.0f, ay = 0.0f;
    int i = 0;
    int n4 = num & ~3;
    for (; i < n4; i += 4) {
        int s0 = srcs[start + i + 0];
        int s1 = srcs[start + i + 1];
        int s2 = srcs[start + i + 2];
        int s3 = srcs[start + i + 3];
        float2 v0 = *(const float2*)&A[(size_t)s0 * lda + c0];
        float2 v1 = *(const float2*)&A[(size_t)s1 * lda + c0];
        float2 v2 = *(const float2*)&A[(size_t)s2 * lda + c0];
        float2 v3 = *(const float2*)&A[(size_t)s3 * lda + c0];
        ax += v0.x + v1.x + v2.x + v3.x;
        ay += v0.y + v1.y + v2.y + v3.y;
    }
    for (; i < num; i++) {
        int s = srcs[start + i];
        float2 v = *(const float2*)&A[(size_t)s * lda + c0];
        ax += v.x;
        ay += v.y;
    }
    float inv = invin[gw];
    float r0 = R[(size_t)gw * ldr + c0];
    float r1 = R[(size_t)gw * ldr + c1];
    float s0 = gam[c0] * rsqrtf(var[c0] + EPSV);
    float s1 = gam[c1] * rsqrtf(var[c1] + EPSV);
    float v0 = (ax * inv + bias[c0] + r0 - mea[c0]) * s0 + bet[c0];
    float v1 = (ay * inv + bias[c1] + r1 - mea[c1]) * s1 + bet[c1];
    v0 = fmaxf(v0, 0.0f);
    v1 = fmaxf(v1, 0.0f);
    if (hprev) {
        v0 += hprev[(size_t)gw * ldh + c0];
        v1 += hprev[(size_t)gw * ldh + c1];
    }
    out[(size_t)gw * ldo + c0] = v0;
    out[(size_t)gw * ldo + c1] = v1;
}

// ---------------- rank head: score = t @ W2 + b2 ----------------
__global__ void k_rankdot(const float* __restrict__ t, const float* __restrict__ W2,
                          const float* __restrict__ b2, float* __restrict__ out, int n) {
    int gw = (blockIdx.x * blockDim.x + threadIdx.x) >> 5;
    int lane = threadIdx.x & 31;
    if (gw >= n) return;
    int c = lane * 2;
    float2 tv = *(const float2*)&t[(size_t)gw * 64 + c];
    float s = tv.x * W2[c] + tv.y * W2[c + 1];
#pragma unroll
    for (int o = 16; o > 0; o >>= 1) s += __shfl_xor_sync(0xffffffffu, s, o);
    if (lane == 0) out[gw] = s + b2[0];
}

// ---------------- regressor tail ----------------
__global__ void k_regfinal(const float* __restrict__ pre, const float* __restrict__ w1last,
                           const float* __restrict__ b1, const float* __restrict__ score,
                           const float* __restrict__ W2, const float* __restrict__ b2,
                           const float* __restrict__ W3, const float* __restrict__ b3,
                           float* __restrict__ preds, int n) {
    __shared__ float h1s[8][66];
    int wmy = threadIdx.x >> 5;
    int lane = threadIdx.x & 31;
    int node = blockIdx.x * 8 + wmy;
    if (node >= n) return;
    float sc = score[node];
    int c = lane * 2;
    float a0 = pre[(size_t)node * 64 + c]     + sc * w1last[c]     + b1[c];
    float a1 = pre[(size_t)node * 64 + c + 1] + sc * w1last[c + 1] + b1[c + 1];
    h1s[wmy][c]     = fmaxf(a0, 0.0f);
    h1s[wmy][c + 1] = fmaxf(a1, 0.0f);
    __syncwarp();
    float h2 = b2[lane];
#pragma unroll 8
    for (int k = 0; k < 64; k++) h2 += h1s[wmy][k] * W2[k * 32 + lane];
    h2 = fmaxf(h2, 0.0f);
    float p = h2 * W3[lane];
#pragma unroll
    for (int o = 16; o > 0; o >>= 1) p += __shfl_xor_sync(0xffffffffu, p, o);
    if (lane == 0) preds[node] = p + b3[0];
}

// ---------------- host ----------------
extern "C" void kernel_launch(void* const* d_in, const int* in_sizes, int n_in,
                              void* d_out, int out_size) {
    const float* x        = (const float*)d_in[0];
    const int*   ei       = (const int*)d_in[1];
    const float* W_in     = (const float*)d_in[2];
    const float* b_in     = (const float*)d_in[3];
    const float* sage_Wl  = (const float*)d_in[4];
    const float* sage_bl  = (const float*)d_in[5];
    const float* sage_Wr  = (const float*)d_in[6];
    const float* bn_g     = (const float*)d_in[7];
    const float* bn_b     = (const float*)d_in[8];
    const float* bn_m     = (const float*)d_in[9];
    const float* bn_v     = (const float*)d_in[10];
    const float* vW_l     = (const float*)d_in[11];
    const float* vb_l     = (const float*)d_in[12];
    const float* vW_r     = (const float*)d_in[13];
    const float* vbn_g    = (const float*)d_in[14];
    const float* vbn_b    = (const float*)d_in[15];
    const float* vbn_m    = (const float*)d_in[16];
    const float* vbn_v    = (const float*)d_in[17];
    const float* W_mu     = (const float*)d_in[18];
    const float* b_mu     = (const float*)d_in[19];
    const float* W_lv     = (const float*)d_in[20];
    const float* b_lv     = (const float*)d_in[21];
    const float* rank_W1  = (const float*)d_in[22];
    const float* rank_b1  = (const float*)d_in[23];
    const float* rank_W2  = (const float*)d_in[24];
    const float* rank_b2  = (const float*)d_in[25];
    const float* reg_W1   = (const float*)d_in[26];
    const float* reg_b1   = (const float*)d_in[27];
    const float* reg_W2   = (const float*)d_in[28];
    const float* reg_b2   = (const float*)d_in[29];
    const float* reg_W3   = (const float*)d_in[30];
    const float* reg_b3   = (const float*)d_in[31];

    int n = in_sizes[0] / 64;
    int e = in_sizes[1] / 2;
    const int* rowv = ei;
    const int* colv = ei + e;

    float *pr, *stage1, *bufA, *bufB, *vbuf, *tbuf, *invin, *invout;
    int *indeg, *outdeg, *off, *cursor, *srcs, *bsum;
    cudaGetSymbolAddress((void**)&pr, g_pr);
    cudaGetSymbolAddress((void**)&stage1, g_stage1);
    cudaGetSymbolAddress((void**)&bufA, g_bufA);
    cudaGetSymbolAddress((void**)&bufB, g_bufB);
    cudaGetSymbolAddress((void**)&vbuf, g_v);
    cudaGetSymbolAddress((void**)&tbuf, g_t);
    cudaGetSymbolAddress((void**)&invin, g_invin);
    cudaGetSymbolAddress((void**)&invout, g_invout);
    cudaGetSymbolAddress((void**)&indeg, g_indeg);
    cudaGetSymbolAddress((void**)&outdeg, g_outdeg);
    cudaGetSymbolAddress((void**)&off, g_off);
    cudaGetSymbolAddress((void**)&cursor, g_cursor);
    cudaGetSymbolAddress((void**)&srcs, g_srcs);
    cudaGetSymbolAddress((void**)&bsum, g_bsum);

    float* out_preds = (float*)d_out;
    float* out_rank  = out_preds + n;
    float* out_mu    = out_preds + 2 * (size_t)n;
    float* out_lv    = out_mu + 64 * (size_t)n;

    // ---- graph build: degrees + CSC by destination ----
    cudaMemsetAsync(indeg, 0, n * sizeof(int), 0);
    cudaMemsetAsync(outdeg, 0, n * sizeof(int), 0);
    k_count<<<(e + 255) / 256, 256>>>(rowv, colv, indeg, outdeg, e);
    int nb = (n + 1023) / 1024;
    k_scan1<<<nb, 1024>>>(indeg, off, bsum, n);
    k_scan2<<<1, 32>>>(bsum, nb);
    k_scan3<<<nb, 1024>>>(off, bsum, cursor, n);
    k_fill<<<(e + 255) / 256, 256>>>(rowv, colv, cursor, srcs, e);
    k_inv<<<(n + 255) / 256, 256>>>(indeg, outdeg, invin, invout, n);

    int ntiles = (n + 63) / 64;
    int gg = ntiles < 592 ? ntiles : 592;
    int gwb = (n * 32 + 255) / 256;

    // ---- inp_skip -> stage1[:,256:320] ----
    k_gemm<64, false><<<gg, 256>>>(x, 64, 64, x, 64, 0, W_in, nullptr, b_in, nullptr,
                                   stage1 + 256, 320, nullptr, 0, n, ntiles);

    // ---- 4 SAGE layers: fused [Wl|Wr] gemm + fused gather/bn/relu/residual ----
    const float* h = x;
    int lh = 64;
    for (int i = 0; i < 4; i++) {
        k_gemm<128, false><<<gg, 256>>>(h, lh, 64, h, lh, 0,
                                        sage_Wl + (size_t)i * 4096, sage_Wr + (size_t)i * 4096,
                                        nullptr, nullptr, pr, 128, pr + 64, 128, n, ntiles);
        k_gatherpost<<<gwb, 256>>>(off, indeg, srcs, pr, 128, pr + 64, 128, invin,
                                   sage_bl + i * 64, bn_g + i * 64, bn_b + i * 64,
                                   bn_m + i * 64, bn_v + i * 64,
                                   h, lh, stage1 + i * 64, 320, n);
        h = stage1 + i * 64;
        lh = 320;
    }

    // ---- path_agg: 4 degree-normalized propagation steps ----
    k_gather<<<gwb, 256>>>(off, indeg, srcs, stage1 + 192, 320, invout, bufA, 64, n);
    k_gather<<<gwb, 256>>>(off, indeg, srcs, bufA, 64, invout, bufB, 64, n);
    k_gather<<<gwb, 256>>>(off, indeg, srcs, bufB, 64, invout, bufA, 64, n);
    k_gather<<<gwb, 256>>>(off, indeg, srcs, bufA, 64, invout, bufB, 64, n);

    // ---- VGAE sage: project-then-aggregate, fused [vW_l|vW_r], K=320+64 ----
    k_gemm<128, false><<<gg, 256>>>(stage1, 320, 320, bufB, 64, 64, vW_l, vW_r,
                                    nullptr, nullptr, pr, 128, pr + 64, 128, n, ntiles);
    k_gatherpost<<<gwb, 256>>>(off, indeg, srcs, pr, 128, pr + 64, 128, invin,
                               vb_l, vbn_g, vbn_b, vbn_m, vbn_v,
                               nullptr, 0, vbuf, 64, n);

    // ---- heads: fused [W_mu|W_lv] ----
    k_gemm<128, false><<<gg, 256>>>(vbuf, 64, 64, vbuf, 64, 0, W_mu, W_lv, b_mu, b_lv,
                                    out_mu, 64, out_lv, 64, n, ntiles);

    k_gemm<64, true><<<gg, 256>>>(out_mu, 64, 64, out_mu, 64, 0, rank_W1, nullptr,
                                  rank_b1, nullptr, tbuf, 64, nullptr, 0, n, ntiles);
    k_rankdot<<<gwb, 256>>>(tbuf, rank_W2, rank_b2, out_rank, n);

    // ---- regressor: pre = stage1@W1[0:320] + mu@W1[320:384] (K-concat fused) ----
    k_gemm<64, false><<<gg, 256>>>(stage1, 320, 320, out_mu, 64, 64, reg_W1, nullptr,
                                   nullptr, nullptr, bufA, 64, nullptr, 0, n, ntiles);
    k_regfinal<<<(n + 7) / 8, 256>>>(bufA, reg_W1 + 384 * 64, reg_b1, out_rank,
                                     reg_W2, reg_b2, reg_W3, reg_b3, out_preds, n);
}

// round 4
// speedup vs baseline: 1.8363x; 1.3891x over previous
#include <cuda_runtime.h>
#include <cuda_fp16.h>
#include <cstdint>
#include <cstddef>

#define MAXN 50000
#define MAXE 800000
#define EPSV 1e-5f
#define PADH 72   // halfs per smem row (bank-conflict-free fragment addressing)

// ---------------- scratch ----------------
__device__ float  g_pr[MAXN * 128];
__device__ float  g_bufA[MAXN * 64];
__device__ float  g_bufB[MAXN * 64];
__device__ float  g_t[MAXN * 64];
__device__ __half g_xh[MAXN * 64],  g_xl[MAXN * 64];
__device__ __half g_s1h[MAXN * 320], g_s1l[MAXN * 320];
__device__ __half g_bh[MAXN * 64],  g_bl2[MAXN * 64];
__device__ __half g_vh[MAXN * 64],  g_vl[MAXN * 64];
__device__ __half g_mh[MAXN * 64],  g_ml[MAXN * 64];
#define TOTW 122880
__device__ __half g_wh[TOTW], g_wl[TOTW];
__device__ float  g_invin[MAXN], g_invout[MAXN];
__device__ int    g_indeg[MAXN], g_outdeg[MAXN], g_off[MAXN], g_cursor[MAXN];
__device__ int    g_srcs[MAXE], g_bsum[64];

// weight region offsets ([64][K] n-major transposed layout)
#define OFF_WIN 0
#define OFF_SWL 4096
#define OFF_SWR 20480
#define OFF_VWL 36864
#define OFF_VWR 61440
#define OFF_WMU 86016
#define OFF_WLV 90112
#define OFF_RNK 94208
#define OFF_REG 98304

__device__ __forceinline__ void split_hl(float v, __half& h, __half& l) {
    h = __float2half_rn(v);
    l = __float2half_rn(v - __half2float(h));
}

// ---------------- graph build ----------------
__global__ void k_count(const int* __restrict__ rowv, const int* __restrict__ colv,
                        int* __restrict__ indeg, int* __restrict__ outdeg, int e) {
    int i = blockIdx.x * blockDim.x + threadIdx.x;
    if (i < e) {
        atomicAdd(&indeg[colv[i]], 1);
        atomicAdd(&outdeg[rowv[i]], 1);
    }
}
__global__ void k_scan1(const int* __restrict__ cnt, int* __restrict__ exc,
                        int* __restrict__ bsum, int n) {
    __shared__ int sh[1024];
    int t = threadIdx.x;
    int i = blockIdx.x * 1024 + t;
    int v = (i < n) ? cnt[i] : 0;
    sh[t] = v;
    __syncthreads();
    for (int d = 1; d < 1024; d <<= 1) {
        int x = (t >= d) ? sh[t - d] : 0;
        __syncthreads();
        sh[t] += x;
        __syncthreads();
    }
    if (i < n) exc[i] = sh[t] - v;
    if (t == 1023) bsum[blockIdx.x] = sh[t];
}
__global__ void k_scan2(int* bsum, int nb) {
    if (threadIdx.x == 0 && blockIdx.x == 0) {
        int run = 0;
        for (int i = 0; i < nb; i++) { int v = bsum[i]; bsum[i] = run; run += v; }
    }
}
__global__ void k_scan3(int* __restrict__ exc, const int* __restrict__ bsum,
                        int* __restrict__ cursor, int n) {
    int i = blockIdx.x * 1024 + threadIdx.x;
    if (i < n) {
        int v = exc[i] + bsum[blockIdx.x];
        exc[i] = v;
        cursor[i] = v;
    }
}
__global__ void k_fill(const int* __restrict__ rowv, const int* __restrict__ colv,
                       int* __restrict__ cursor, int* __restrict__ srcs, int e) {
    int i = blockIdx.x * blockDim.x + threadIdx.x;
    if (i < e) {
        int c = colv[i];
        int pos = atomicAdd(&cursor[c], 1);
        srcs[pos] = rowv[i];
    }
}
__global__ void k_inv(const int* __restrict__ indeg, const int* __restrict__ outdeg,
                      float* __restrict__ invin, float* __restrict__ invout, int n) {
    int i = blockIdx.x * blockDim.x + threadIdx.x;
    if (i < n) {
        invin[i]  = 1.0f / (float)max(indeg[i], 1);
        invout[i] = 1.0f / (float)max(outdeg[i], 1);
    }
}

// ---------------- converters ----------------
__global__ void k_cvtx(const float* __restrict__ x, __half* __restrict__ h,
                       __half* __restrict__ l, int tot) {
    int i = blockIdx.x * blockDim.x + threadIdx.x;
    if (i < tot) split_hl(x[i], h[i], l[i]);
}

// transpose+split all weights into [64][K] n-major fp16 hi/lo
__global__ void k_cvtw(const float* W_in, const float* sWl, const float* sWr,
                       const float* vWl, const float* vWr, const float* Wmu,
                       const float* Wlv, const float* rW1, const float* gW1,
                       __half* __restrict__ wh, __half* __restrict__ wl) {
    int t = blockIdx.x * blockDim.x + threadIdx.x;
    if (t >= TOTW) return;
    const float* src; int K, off, idx;
    if (t < OFF_SWL)      { src = W_in; K = 64; off = OFF_WIN; idx = t; }
    else if (t < OFF_SWR) { int lo = t - OFF_SWL, s = lo >> 12; src = sWl + s * 4096; K = 64; off = OFF_SWL + s * 4096; idx = lo & 4095; }
    else if (t < OFF_VWL) { int lo = t - OFF_SWR, s = lo >> 12; src = sWr + s * 4096; K = 64; off = OFF_SWR + s * 4096; idx = lo & 4095; }
    else if (t < OFF_VWR) { src = vWl; K = 384; off = OFF_VWL; idx = t - OFF_VWL; }
    else if (t < OFF_WMU) { src = vWr; K = 384; off = OFF_VWR; idx = t - OFF_VWR; }
    else if (t < OFF_WLV) { src = Wmu; K = 64; off = OFF_WMU; idx = t - OFF_WMU; }
    else if (t < OFF_RNK) { src = Wlv; K = 64; off = OFF_WLV; idx = t - OFF_WLV; }
    else if (t < OFF_REG) { src = rW1; K = 64; off = OFF_RNK; idx = t - OFF_RNK; }
    else                  { src = gW1; K = 384; off = OFF_REG; idx = t - OFF_REG; }
    int col = idx / K;
    int k = idx - col * K;
    __half h, l;
    split_hl(src[(size_t)k * 64 + col], h, l);
    wh[off + col * K + k] = h;
    wl[off + col * K + k] = l;
}

// ---------------- HMMA GEMM ----------------
// C[n, NCOLS] = [A1|A2][n, K1+K2] @ W  via fp16 hi/lo split: h·h + h·l + l·h.
// Tile 128 rows x NCOLS, 256 threads: 4 row-warps x 2 col-warps.
__device__ __forceinline__ void mma16816(float* d, const uint32_t* a,
                                         uint32_t b0, uint32_t b1) {
    asm volatile(
        "mma.sync.aligned.m16n8k16.row.col.f32.f16.f16.f32 "
        "{%0,%1,%2,%3}, {%4,%5,%6,%7}, {%8,%9}, {%0,%1,%2,%3};"
        : "+f"(d[0]), "+f"(d[1]), "+f"(d[2]), "+f"(d[3])
        : "r"(a[0]), "r"(a[1]), "r"(a[2]), "r"(a[3]), "r"(b0), "r"(b1));
}

template<int NCOLS, bool RELU>
__global__ void __launch_bounds__(256)
k_mmagemm(const __half* __restrict__ Ah1, const __half* __restrict__ Al1, int lda1, int K1,
          const __half* __restrict__ Ah2, const __half* __restrict__ Al2, int lda2, int K2,
          const __half* __restrict__ Wh_a, const __half* __restrict__ Wl_a,
          const __half* __restrict__ Wh_b, const __half* __restrict__ Wl_b, int Kw,
          const float* __restrict__ ba, const float* __restrict__ bb,
          float* __restrict__ C1, int ldc1, float* __restrict__ C2, int ldc2,
          __half* __restrict__ C1h, __half* __restrict__ C1l, int ldc1p,
          int n, int ntiles)
{
    constexpr int NB = NCOLS / 16;     // n-blocks per col-warp
    extern __shared__ char smem[];
    __half* sAh = (__half*)smem;
    __half* sAl = sAh + 128 * PADH;
    __half* sBh = sAl + 128 * PADH;
    __half* sBl = sBh + NCOLS * PADH;

    const int tid = threadIdx.x;
    const int lane = tid & 31;
    const int rw = (tid >> 5) & 3;
    const int cw = tid >> 7;
    const int g = lane >> 2, q = lane & 3;
    const int nch = (K1 + K2) >> 6;

    for (int tile = blockIdx.x; tile < ntiles; tile += gridDim.x) {
        float acc[2][NB][4];
#pragma unroll
        for (int mb = 0; mb < 2; mb++)
#pragma unroll
            for (int nb = 0; nb < NB; nb++)
#pragma unroll
                for (int j = 0; j < 4; j++) acc[mb][nb][j] = 0.0f;

        for (int ch = 0; ch < nch; ch++) {
            const int kb = ch << 6;
            const __half* Ah; const __half* Al; int lda, kloc;
            if (kb < K1) { Ah = Ah1; Al = Al1; lda = lda1; kloc = kb; }
            else         { Ah = Ah2; Al = Al2; lda = lda2; kloc = kb - K1; }

            __syncthreads();
            // stage A: 128 rows x 64 k (hi+lo), 16B vectors
            for (int u = tid; u < 1024; u += 256) {
                int row = u >> 3, k8 = (u & 7) << 3;
                int node = tile * 128 + row;
                uint4 vh = make_uint4(0, 0, 0, 0), vl = vh;
                if (node < n) {
                    vh = *(const uint4*)(Ah + (size_t)node * lda + kloc + k8);
                    vl = *(const uint4*)(Al + (size_t)node * lda + kloc + k8);
                }
                *(uint4*)(sAh + row * PADH + k8) = vh;
                *(uint4*)(sAl + row * PADH + k8) = vl;
            }
            // stage B: NCOLS rows x 64 k
            for (int u = tid; u < NCOLS * 8; u += 256) {
                int nn = u >> 3, k8 = (u & 7) << 3;
                const __half* wrh;
                const __half* wrl;
                if (NCOLS == 64 || nn < 64) { wrh = Wh_a + (size_t)nn * Kw; wrl = Wl_a + (size_t)nn * Kw; }
                else { wrh = Wh_b + (size_t)(nn - 64) * Kw; wrl = Wl_b + (size_t)(nn - 64) * Kw; }
                *(uint4*)(sBh + nn * PADH + k8) = *(const uint4*)(wrh + kb + k8);
                *(uint4*)(sBl + nn * PADH + k8) = *(const uint4*)(wrl + kb + k8);
            }
            __syncthreads();

#pragma unroll
            for (int ks = 0; ks < 4; ks++) {
                const int ko = ks * 16 + 2 * q;
                uint32_t fah[2][4], fal[2][4];
#pragma unroll
                for (int mb = 0; mb < 2; mb++) {
                    int r0 = rw * 32 + mb * 16 + g;
                    const __half* pa = sAh + r0 * PADH + ko;
                    const __half* pl = sAl + r0 * PADH + ko;
                    fah[mb][0] = *(const uint32_t*)pa;
                    fah[mb][1] = *(const uint32_t*)(pa + 8 * PADH);
                    fah[mb][2] = *(const uint32_t*)(pa + 8);
                    fah[mb][3] = *(const uint32_t*)(pa + 8 * PADH + 8);
                    fal[mb][0] = *(const uint32_t*)pl;
                    fal[mb][1] = *(const uint32_t*)(pl + 8 * PADH);
                    fal[mb][2] = *(const uint32_t*)(pl + 8);
                    fal[mb][3] = *(const uint32_t*)(pl + 8 * PADH + 8);
                }
#pragma unroll
                for (int nb = 0; nb < NB; nb++) {
                    int nc = cw * (NCOLS / 2) + nb * 8 + g;
                    const __half* pb = sBh + nc * PADH + ko;
                    const __half* pbl = sBl + nc * PADH + ko;
                    uint32_t bh0 = *(const uint32_t*)pb;
                    uint32_t bh1 = *(const uint32_t*)(pb + 8);
                    uint32_t bl0 = *(const uint32_t*)pbl;
                    uint32_t bl1 = *(const uint32_t*)(pbl + 8);
#pragma unroll
                    for (int mb = 0; mb < 2; mb++) {
                        mma16816(acc[mb][nb], fah[mb], bh0, bh1);
                        mma16816(acc[mb][nb], fah[mb], bl0, bl1);
                        mma16816(acc[mb][nb], fal[mb], bh0, bh1);
                    }
                }
            }
        }

        // epilogue
#pragma unroll
        for (int mb = 0; mb < 2; mb++) {
#pragma unroll
            for (int nb = 0; nb < NB; nb++) {
                int r0 = tile * 128 + rw * 32 + mb * 16 + g;
                int gc = cw * (NCOLS / 2) + nb * 8 + 2 * q;
                float* C; const float* bs; int ldc, col;
                __half* Ch = nullptr; __half* Cl = nullptr; int ldp = 0;
                if (NCOLS == 128 && gc >= 64) { C = C2; bs = bb; ldc = ldc2; col = gc - 64; }
                else { C = C1; bs = ba; ldc = ldc1; col = gc; Ch = C1h; Cl = C1l; ldp = ldc1p; }
                float b0 = bs ? bs[col] : 0.0f;
                float b1 = bs ? bs[col + 1] : 0.0f;
#pragma unroll
                for (int hh = 0; hh < 2; hh++) {
                    int r = r0 + hh * 8;
                    if (r >= n) continue;
                    float v0 = acc[mb][nb][2 * hh + 0] + b0;
                    float v1 = acc[mb][nb][2 * hh + 1] + b1;
                    if (RELU) { v0 = fmaxf(v0, 0.f); v1 = fmaxf(v1, 0.f); }
                    if (C) *(float2*)&C[(size_t)r * ldc + col] = make_float2(v0, v1);
                    if (Ch) {
                        __half h0, l0, h1, l1;
                        split_hl(v0, h0, l0);
                        split_hl(v1, h1, l1);
                        *(__half2*)&Ch[(size_t)r * ldp + col] = __halves2half2(h0, h1);
                        *(__half2*)&Cl[(size_t)r * ldp + col] = __halves2half2(l0, l1);
                    }
                }
            }
        }
    }
}

// ---------------- CSC gather (path steps) ----------------
template<bool INPAIR>
__global__ void k_gather(const int* __restrict__ off, const int* __restrict__ cnt,
                         const int* __restrict__ srcs,
                         const float* __restrict__ Af,
                         const __half* __restrict__ Ah, const __half* __restrict__ Al,
                         int lda, const float* __restrict__ sscale,
                         float* __restrict__ outf,
                         __half* __restrict__ outh, __half* __restrict__ outl,
                         int ldo, int n) {
    int gw = (blockIdx.x * blockDim.x + threadIdx.x) >> 5;
    int lane = threadIdx.x & 31;
    if (gw >= n) return;
    int start = off[gw];
    int num = cnt[gw];
    int c2 = lane * 2;
    float ax = 0.0f, ay = 0.0f;
    for (int i = 0; i < num; i++) {
        int s = srcs[start + i];
        float w = sscale[s];
        float2 v;
        if (INPAIR) {
            float2 h = __half22float2(*(const __half2*)&Ah[(size_t)s * lda + c2]);
            float2 l = __half22float2(*(const __half2*)&Al[(size_t)s * lda + c2]);
            v = make_float2(h.x + l.x, h.y + l.y);
        } else {
            v = *(const float2*)&Af[(size_t)s * lda + c2];
        }
        ax += v.x * w;
        ay += v.y * w;
    }
    if (outf) *(float2*)&outf[(size_t)gw * ldo + c2] = make_float2(ax, ay);
    if (outh) {
        __half h0, l0, h1, l1;
        split_hl(ax, h0, l0);
        split_hl(ay, h1, l1);
        *(__half2*)&outh[(size_t)gw * ldo + c2] = __halves2half2(h0, h1);
        *(__half2*)&outl[(size_t)gw * ldo + c2] = __halves2half2(l0, l1);
    }
}

// ---------------- fused gather + SAGE epilogue (pairs out) ----------------
__global__ void k_gatherpost(const int* __restrict__ off, const int* __restrict__ cnt,
                             const int* __restrict__ srcs,
                             const float* __restrict__ A, int lda,
                             const float* __restrict__ R, int ldr,
                             const float* __restrict__ invin,
                             const float* __restrict__ bias,
                             const float* __restrict__ gam, const float* __restrict__ bet,
                             const float* __restrict__ mea, const float* __restrict__ var,
                             const __half* __restrict__ hh, const __half* __restrict__ hl,
                             int ldh,
                             __half* __restrict__ outh, __half* __restrict__ outl,
                             int ldo, int n) {
    int gw = (blockIdx.x * blockDim.x + threadIdx.x) >> 5;
    int lane = threadIdx.x & 31;
    if (gw >= n) return;
    int start = off[gw];
    int num = cnt[gw];
    int c0 = lane * 2, c1 = c0 + 1;
    float ax = 0.0f, ay = 0.0f;
    int i = 0;
    int n4 = num & ~3;
    for (; i < n4; i += 4) {
        int s0 = srcs[start + i + 0];
        int s1 = srcs[start + i + 1];
        int s2 = srcs[start + i + 2];
        int s3 = srcs[start + i + 3];
        float2 v0 = *(const float2*)&A[(size_t)s0 * lda + c0];
        float2 v1 = *(const float2*)&A[(size_t)s1 * lda + c0];
        float2 v2 = *(const float2*)&A[(size_t)s2 * lda + c0];
        float2 v3 = *(const float2*)&A[(size_t)s3 * lda + c0];
        ax += v0.x + v1.x + v2.x + v3.x;
        ay += v0.y + v1.y + v2.y + v3.y;
    }
    for (; i < num; i++) {
        int s = srcs[start + i];
        float2 v = *(const float2*)&A[(size_t)s * lda + c0];
        ax += v.x;
        ay += v.y;
    }
    float inv = invin[gw];
    float r0 = R[(size_t)gw * ldr + c0];
    float r1 = R[(size_t)gw * ldr + c1];
    float s0 = gam[c0] * rsqrtf(var[c0] + EPSV);
    float s1 = gam[c1] * rsqrtf(var[c1] + EPSV);
    float v0 = (ax * inv + bias[c0] + r0 - mea[c0]) * s0 + bet[c0];
    float v1 = (ay * inv + bias[c1] + r1 - mea[c1]) * s1 + bet[c1];
    v0 = fmaxf(v0, 0.0f);
    v1 = fmaxf(v1, 0.0f);
    if (hh) {
        float2 ph = __half22float2(*(const __half2*)&hh[(size_t)gw * ldh + c0]);
        float2 pl = __half22float2(*(const __half2*)&hl[(size_t)gw * ldh + c0]);
        v0 += ph.x + pl.x;
        v1 += ph.y + pl.y;
    }
    __half h0, l0, h1, l1;
    split_hl(v0, h0, l0);
    split_hl(v1, h1, l1);
    *(__half2*)&outh[(size_t)gw * ldo + c0] = __halves2half2(h0, h1);
    *(__half2*)&outl[(size_t)gw * ldo + c0] = __halves2half2(l0, l1);
}

// ---------------- rank head ----------------
__global__ void k_rankdot(const float* __restrict__ t, const float* __restrict__ W2,
                          const float* __restrict__ b2, float* __restrict__ out, int n) {
    int gw = (blockIdx.x * blockDim.x + threadIdx.x) >> 5;
    int lane = threadIdx.x & 31;
    if (gw >= n) return;
    int c = lane * 2;
    float2 tv = *(const float2*)&t[(size_t)gw * 64 + c];
    float s = tv.x * W2[c] + tv.y * W2[c + 1];
#pragma unroll
    for (int o = 16; o > 0; o >>= 1) s += __shfl_xor_sync(0xffffffffu, s, o);
    if (lane == 0) out[gw] = s + b2[0];
}

// ---------------- regressor tail ----------------
__global__ void k_regfinal(const float* __restrict__ pre, const float* __restrict__ w1last,
                           const float* __restrict__ b1, const float* __restrict__ score,
                           const float* __restrict__ W2, const float* __restrict__ b2,
                           const float* __restrict__ W3, const float* __restrict__ b3,
                           float* __restrict__ preds, int n) {
    __shared__ float h1s[8][66];
    int wmy = threadIdx.x >> 5;
    int lane = threadIdx.x & 31;
    int node = blockIdx.x * 8 + wmy;
    if (node >= n) return;
    float sc = score[node];
    int c = lane * 2;
    float a0 = pre[(size_t)node * 64 + c]     + sc * w1last[c]     + b1[c];
    float a1 = pre[(size_t)node * 64 + c + 1] + sc * w1last[c + 1] + b1[c + 1];
    h1s[wmy][c]     = fmaxf(a0, 0.0f);
    h1s[wmy][c + 1] = fmaxf(a1, 0.0f);
    __syncwarp();
    float h2 = b2[lane];
#pragma unroll 8
    for (int k = 0; k < 64; k++) h2 += h1s[wmy][k] * W2[k * 32 + lane];
    h2 = fmaxf(h2, 0.0f);
    float p = h2 * W3[lane];
#pragma unroll
    for (int o = 16; o > 0; o >>= 1) p += __shfl_xor_sync(0xffffffffu, p, o);
    if (lane == 0) preds[node] = p + b3[0];
}

// ---------------- host ----------------
static const int SMEM128 = (128 + 128) * PADH * 2 * 2;  // 73728
static const int SMEM64  = (128 + 64) * PADH * 2 * 2;   // 55296

extern "C" void kernel_launch(void* const* d_in, const int* in_sizes, int n_in,
                              void* d_out, int out_size) {
    const float* x        = (const float*)d_in[0];
    const int*   ei       = (const int*)d_in[1];
    const float* W_in     = (const float*)d_in[2];
    const float* b_in     = (const float*)d_in[3];
    const float* sage_Wl  = (const float*)d_in[4];
    const float* sage_bl  = (const float*)d_in[5];
    const float* sage_Wr  = (const float*)d_in[6];
    const float* bn_g     = (const float*)d_in[7];
    const float* bn_b     = (const float*)d_in[8];
    const float* bn_m     = (const float*)d_in[9];
    const float* bn_v     = (const float*)d_in[10];
    const float* vW_l     = (const float*)d_in[11];
    const float* vb_l     = (const float*)d_in[12];
    const float* vW_r     = (const float*)d_in[13];
    const float* vbn_g    = (const float*)d_in[14];
    const float* vbn_b    = (const float*)d_in[15];
    const float* vbn_m    = (const float*)d_in[16];
    const float* vbn_v    = (const float*)d_in[17];
    const float* W_mu     = (const float*)d_in[18];
    const float* b_mu     = (const float*)d_in[19];
    const float* W_lv     = (const float*)d_in[20];
    const float* b_lv     = (const float*)d_in[21];
    const float* rank_W1  = (const float*)d_in[22];
    const float* rank_b1  = (const float*)d_in[23];
    const float* rank_W2  = (const float*)d_in[24];
    const float* rank_b2  = (const float*)d_in[25];
    const float* reg_W1   = (const float*)d_in[26];
    const float* reg_b1   = (const float*)d_in[27];
    const float* reg_W2   = (const float*)d_in[28];
    const float* reg_b2   = (const float*)d_in[29];
    const float* reg_W3   = (const float*)d_in[30];
    const float* reg_b3   = (const float*)d_in[31];

    int n = in_sizes[0] / 64;
    int e = in_sizes[1] / 2;
    const int* rowv = ei;
    const int* colv = ei + e;

    cudaFuncSetAttribute(k_mmagemm<128, false>, cudaFuncAttributeMaxDynamicSharedMemorySize, SMEM128);
    cudaFuncSetAttribute(k_mmagemm<64, false>,  cudaFuncAttributeMaxDynamicSharedMemorySize, SMEM64);
    cudaFuncSetAttribute(k_mmagemm<64, true>,   cudaFuncAttributeMaxDynamicSharedMemorySize, SMEM64);

    float *pr, *bufA, *bufB, *tbuf, *invin, *invout;
    __half *xh, *xl, *s1h, *s1l, *bh, *bl, *vh, *vl, *mh, *ml, *wh, *wl;
    int *indeg, *outdeg, *off, *cursor, *srcs, *bsum;
    cudaGetSymbolAddress((void**)&pr, g_pr);
    cudaGetSymbolAddress((void**)&bufA, g_bufA);
    cudaGetSymbolAddress((void**)&bufB, g_bufB);
    cudaGetSymbolAddress((void**)&tbuf, g_t);
    cudaGetSymbolAddress((void**)&xh, g_xh);
    cudaGetSymbolAddress((void**)&xl, g_xl);
    cudaGetSymbolAddress((void**)&s1h, g_s1h);
    cudaGetSymbolAddress((void**)&s1l, g_s1l);
    cudaGetSymbolAddress((void**)&bh, g_bh);
    cudaGetSymbolAddress((void**)&bl, g_bl2);
    cudaGetSymbolAddress((void**)&vh, g_vh);
    cudaGetSymbolAddress((void**)&vl, g_vl);
    cudaGetSymbolAddress((void**)&mh, g_mh);
    cudaGetSymbolAddress((void**)&ml, g_ml);
    cudaGetSymbolAddress((void**)&wh, g_wh);
    cudaGetSymbolAddress((void**)&wl, g_wl);
    cudaGetSymbolAddress((void**)&invin, g_invin);
    cudaGetSymbolAddress((void**)&invout, g_invout);
    cudaGetSymbolAddress((void**)&indeg, g_indeg);
    cudaGetSymbolAddress((void**)&outdeg, g_outdeg);
    cudaGetSymbolAddress((void**)&off, g_off);
    cudaGetSymbolAddress((void**)&cursor, g_cursor);
    cudaGetSymbolAddress((void**)&srcs, g_srcs);
    cudaGetSymbolAddress((void**)&bsum, g_bsum);

    float* out_preds = (float*)d_out;
    float* out_rank  = out_preds + n;
    float* out_mu    = out_preds + 2 * (size_t)n;
    float* out_lv    = out_mu + 64 * (size_t)n;

    // ---- graph build + converters ----
    cudaMemsetAsync(indeg, 0, n * sizeof(int), 0);
    cudaMemsetAsync(outdeg, 0, n * sizeof(int), 0);
    k_count<<<(e + 255) / 256, 256>>>(rowv, colv, indeg, outdeg, e);
    int nb = (n + 1023) / 1024;
    k_scan1<<<nb, 1024>>>(indeg, off, bsum, n);
    k_scan2<<<1, 32>>>(bsum, nb);
    k_scan3<<<nb, 1024>>>(off, bsum, cursor, n);
    k_fill<<<(e + 255) / 256, 256>>>(rowv, colv, cursor, srcs, e);
    k_inv<<<(n + 255) / 256, 256>>>(indeg, outdeg, invin, invout, n);
    k_cvtx<<<(n * 64 + 255) / 256, 256>>>(x, xh, xl, n * 64);
    k_cvtw<<<(TOTW + 255) / 256, 256>>>(W_in, sage_Wl, sage_Wr, vW_l, vW_r,
                                        W_mu, W_lv, rank_W1, reg_W1, wh, wl);

    int ntiles = (n + 127) / 128;
    int gg = ntiles < 296 ? ntiles : 296;
    int gwb = (n * 32 + 255) / 256;

    // ---- inp_skip -> s1 pairs cols [256,320) ----
    k_mmagemm<64, false><<<gg, 256, SMEM64>>>(
        xh, xl, 64, 64, nullptr, nullptr, 0, 0,
        wh + OFF_WIN, wl + OFF_WIN, nullptr, nullptr, 64,
        b_in, nullptr, nullptr, 0, nullptr, 0, s1h + 256, s1l + 256, 320, n, ntiles);

    // ---- 4 SAGE layers ----
    const __half* hhp = xh; const __half* hlp = xl;
    int lh = 64, hofs = 0;
    for (int i = 0; i < 4; i++) {
        k_mmagemm<128, false><<<gg, 256, SMEM128>>>(
            hhp + hofs, hlp + hofs, lh, 64, nullptr, nullptr, 0, 0,
            wh + OFF_SWL + i * 4096, wl + OFF_SWL + i * 4096,
            wh + OFF_SWR + i * 4096, wl + OFF_SWR + i * 4096, 64,
            nullptr, nullptr, pr, 128, pr + 64, 128, nullptr, nullptr, 0, n, ntiles);
        k_gatherpost<<<gwb, 256>>>(off, indeg, srcs, pr, 128, pr + 64, 128, invin,
                                   sage_bl + i * 64, bn_g + i * 64, bn_b + i * 64,
                                   bn_m + i * 64, bn_v + i * 64,
                                   hhp + hofs, hlp + hofs, lh,
                                   s1h + i * 64, s1l + i * 64, 320, n);
        hhp = s1h; hlp = s1l; lh = 320; hofs = i * 64;
    }

    // ---- path_agg: 4 steps (first reads s1 pairs @192; last writes pairs) ----
    k_gather<true><<<gwb, 256>>>(off, indeg, srcs, nullptr, s1h + 192, s1l + 192, 320,
                                 invout, bufA, nullptr, nullptr, 64, n);
    k_gather<false><<<gwb, 256>>>(off, indeg, srcs, bufA, nullptr, nullptr, 64,
                                  invout, bufB, nullptr, nullptr, 64, n);
    k_gather<false><<<gwb, 256>>>(off, indeg, srcs, bufB, nullptr, nullptr, 64,
                                  invout, bufA, nullptr, nullptr, 64, n);
    k_gather<false><<<gwb, 256>>>(off, indeg, srcs, bufA, nullptr, nullptr, 64,
                                  invout, nullptr, bh, bl, 64, n);

    // ---- VGAE sage: [s1|bufB] (K=320+64) @ [vW_l|vW_r] ----
    k_mmagemm<128, false><<<gg, 256, SMEM128>>>(
        s1h, s1l, 320, 320, bh, bl, 64, 64,
        wh + OFF_VWL, wl + OFF_VWL, wh + OFF_VWR, wl + OFF_VWR, 384,
        nullptr, nullptr, pr, 128, pr + 64, 128, nullptr, nullptr, 0, n, ntiles);
    k_gatherpost<<<gwb, 256>>>(off, indeg, srcs, pr, 128, pr + 64, 128, invin,
                               vb_l, vbn_g, vbn_b, vbn_m, vbn_v,
                               nullptr, nullptr, 0, vh, vl, 64, n);

    // ---- heads: [W_mu|W_lv]; mu also as pairs ----
    k_mmagemm<128, false><<<gg, 256, SMEM128>>>(
        vh, vl, 64, 64, nullptr, nullptr, 0, 0,
        wh + OFF_WMU, wl + OFF_WMU, wh + OFF_WLV, wl + OFF_WLV, 64,
        b_mu, b_lv, out_mu, 64, out_lv, 64, mh, ml, 64, n, ntiles);

    // ---- rank head ----
    k_mmagemm<64, true><<<gg, 256, SMEM64>>>(
        mh, ml, 64, 64, nullptr, nullptr, 0, 0,
        wh + OFF_RNK, wl + OFF_RNK, nullptr, nullptr, 64,
        rank_b1, nullptr, tbuf, 64, nullptr, 0, nullptr, nullptr, 0, n, ntiles);
    k_rankdot<<<gwb, 256>>>(tbuf, rank_W2, rank_b2, out_rank, n);

    // ---- regressor pre: [s1|mu] (K=320+64) @ reg_W1[0:384] ----
    k_mmagemm<64, false><<<gg, 256, SMEM64>>>(
        s1h, s1l, 320, 320, mh, ml, 64, 64,
        wh + OFF_REG, wl + OFF_REG, nullptr, nullptr, 384,
        nullptr, nullptr, bufA, 64, nullptr, 0, nullptr, nullptr, 0, n, ntiles);
    k_regfinal<<<(n + 7) / 8, 256>>>(bufA, reg_W1 + 384 * 64, reg_b1, out_rank,
                                     reg_W2, reg_b2, reg_W3, reg_b3, out_preds, n);
}

// round 5
// speedup vs baseline: 1.9965x; 1.0872x over previous
#include <cuda_runtime.h>
#include <cuda_fp16.h>
#include <cstdint>
#include <cstddef>

#define MAXN 50000
#define MAXE 800000
#define EPSV 1e-5f
#define PADH 72   // halfs per smem row (bank-conflict-free fragment addressing)

// ---------------- scratch ----------------
__device__ float  g_pr[MAXN * 128];
__device__ float  g_bufA[MAXN * 64];
__device__ float  g_t[MAXN * 64];
__device__ __half g_xh[MAXN * 64],  g_xl[MAXN * 64];
__device__ __half g_s1h[MAXN * 320], g_s1l[MAXN * 320];
__device__ __half g_hA[MAXN * 64],  g_hB[MAXN * 64];   // fp16 path buffers
__device__ __half g_bh[MAXN * 64],  g_bl2[MAXN * 64];
__device__ __half g_vh[MAXN * 64],  g_vl[MAXN * 64];
__device__ __half g_mh[MAXN * 64],  g_ml[MAXN * 64];
#define TOTW 122880
__device__ __half g_wh[TOTW], g_wl[TOTW];
__device__ float  g_invin[MAXN], g_invout[MAXN];
__device__ int    g_indeg[MAXN], g_outdeg[MAXN], g_off[MAXN], g_cursor[MAXN];
__device__ int    g_srcs[MAXE], g_bsum[64];

// weight region offsets ([64][K] n-major transposed layout)
#define OFF_WIN 0
#define OFF_SWL 4096
#define OFF_SWR 20480
#define OFF_VWL 36864
#define OFF_VWR 61440
#define OFF_WMU 86016
#define OFF_WLV 90112
#define OFF_RNK 94208
#define OFF_REG 98304

__device__ __forceinline__ void split_hl(float v, __half& h, __half& l) {
    h = __float2half_rn(v);
    l = __float2half_rn(v - __half2float(h));
}

// ---------------- graph build ----------------
__global__ void k_count(const int* __restrict__ rowv, const int* __restrict__ colv,
                        int* __restrict__ indeg, int* __restrict__ outdeg, int e) {
    int i = blockIdx.x * blockDim.x + threadIdx.x;
    if (i < e) {
        atomicAdd(&indeg[colv[i]], 1);
        atomicAdd(&outdeg[rowv[i]], 1);
    }
}
__global__ void k_scan1(const int* __restrict__ cnt, int* __restrict__ exc,
                        int* __restrict__ bsum, int n) {
    __shared__ int sh[1024];
    int t = threadIdx.x;
    int i = blockIdx.x * 1024 + t;
    int v = (i < n) ? cnt[i] : 0;
    sh[t] = v;
    __syncthreads();
    for (int d = 1; d < 1024; d <<= 1) {
        int x = (t >= d) ? sh[t - d] : 0;
        __syncthreads();
        sh[t] += x;
        __syncthreads();
    }
    if (i < n) exc[i] = sh[t] - v;
    if (t == 1023) bsum[blockIdx.x] = sh[t];
}
__global__ void k_scan2(int* bsum, int nb) {
    if (threadIdx.x == 0 && blockIdx.x == 0) {
        int run = 0;
        for (int i = 0; i < nb; i++) { int v = bsum[i]; bsum[i] = run; run += v; }
    }
}
// scan finalize + inverse-degree (fused)
__global__ void k_scan3(int* __restrict__ exc, const int* __restrict__ bsum,
                        int* __restrict__ cursor,
                        const int* __restrict__ indeg, const int* __restrict__ outdeg,
                        float* __restrict__ invin, float* __restrict__ invout, int n) {
    int i = blockIdx.x * 1024 + threadIdx.x;
    if (i < n) {
        int v = exc[i] + bsum[blockIdx.x];
        exc[i] = v;
        cursor[i] = v;
        invin[i]  = 1.0f / (float)max(indeg[i], 1);
        invout[i] = 1.0f / (float)max(outdeg[i], 1);
    }
}
__global__ void k_fill(const int* __restrict__ rowv, const int* __restrict__ colv,
                       int* __restrict__ cursor, int* __restrict__ srcs, int e) {
    int i = blockIdx.x * blockDim.x + threadIdx.x;
    if (i < e) {
        int c = colv[i];
        int pos = atomicAdd(&cursor[c], 1);
        srcs[pos] = rowv[i];
    }
}

// ---------------- converters ----------------
__global__ void k_cvtx(const float* __restrict__ x, __half* __restrict__ h,
                       __half* __restrict__ l, int tot) {
    int i = blockIdx.x * blockDim.x + threadIdx.x;
    if (i < tot) split_hl(x[i], h[i], l[i]);
}
__global__ void k_cvtw(const float* W_in, const float* sWl, const float* sWr,
                       const float* vWl, const float* vWr, const float* Wmu,
                       const float* Wlv, const float* rW1, const float* gW1,
                       __half* __restrict__ wh, __half* __restrict__ wl) {
    int t = blockIdx.x * blockDim.x + threadIdx.x;
    if (t >= TOTW) return;
    const float* src; int K, off, idx;
    if (t < OFF_SWL)      { src = W_in; K = 64; off = OFF_WIN; idx = t; }
    else if (t < OFF_SWR) { int lo = t - OFF_SWL, s = lo >> 12; src = sWl + s * 4096; K = 64; off = OFF_SWL + s * 4096; idx = lo & 4095; }
    else if (t < OFF_VWL) { int lo = t - OFF_SWR, s = lo >> 12; src = sWr + s * 4096; K = 64; off = OFF_SWR + s * 4096; idx = lo & 4095; }
    else if (t < OFF_VWR) { src = vWl; K = 384; off = OFF_VWL; idx = t - OFF_VWL; }
    else if (t < OFF_WMU) { src = vWr; K = 384; off = OFF_VWR; idx = t - OFF_VWR; }
    else if (t < OFF_WLV) { src = Wmu; K = 64; off = OFF_WMU; idx = t - OFF_WMU; }
    else if (t < OFF_RNK) { src = Wlv; K = 64; off = OFF_WLV; idx = t - OFF_WLV; }
    else if (t < OFF_REG) { src = rW1; K = 64; off = OFF_RNK; idx = t - OFF_RNK; }
    else                  { src = gW1; K = 384; off = OFF_REG; idx = t - OFF_REG; }
    int col = idx / K;
    int k = idx - col * K;
    __half h, l;
    split_hl(src[(size_t)k * 64 + col], h, l);
    wh[off + col * K + k] = h;
    wl[off + col * K + k] = l;
}

// ---------------- HMMA GEMM (ldmatrix fragment loads) ----------------
__device__ __forceinline__ void mma16816(float* d, const uint32_t* a,
                                         uint32_t b0, uint32_t b1) {
    asm volatile(
        "mma.sync.aligned.m16n8k16.row.col.f32.f16.f16.f32 "
        "{%0,%1,%2,%3}, {%4,%5,%6,%7}, {%8,%9}, {%0,%1,%2,%3};"
        : "+f"(d[0]), "+f"(d[1]), "+f"(d[2]), "+f"(d[3])
        : "r"(a[0]), "r"(a[1]), "r"(a[2]), "r"(a[3]), "r"(b0), "r"(b1));
}
__device__ __forceinline__ void ldsm4(uint32_t* r, uint32_t a) {
    asm volatile("ldmatrix.sync.aligned.m8n8.x4.shared.b16 {%0,%1,%2,%3}, [%4];"
        : "=r"(r[0]), "=r"(r[1]), "=r"(r[2]), "=r"(r[3]) : "r"(a));
}
__device__ __forceinline__ uint32_t smem_u32(const void* p) {
    uint32_t a;
    asm("{ .reg .u64 t; cvta.to.shared.u64 t, %1; cvt.u32.u64 %0, t; }" : "=r"(a) : "l"(p));
    return a;
}

template<int NCOLS, bool RELU>
__global__ void __launch_bounds__(256)
k_mmagemm(const __half* __restrict__ Ah1, const __half* __restrict__ Al1, int lda1, int K1,
          const __half* __restrict__ Ah2, const __half* __restrict__ Al2, int lda2, int K2,
          const __half* __restrict__ Wh_a, const __half* __restrict__ Wl_a,
          const __half* __restrict__ Wh_b, const __half* __restrict__ Wl_b, int Kw,
          const float* __restrict__ ba, const float* __restrict__ bb,
          float* __restrict__ C1, int ldc1, float* __restrict__ C2, int ldc2,
          __half* __restrict__ C1h, __half* __restrict__ C1l, int ldc1p,
          int n, int ntiles)
{
    constexpr int NB = NCOLS / 16;
    extern __shared__ char smem[];
    __half* sAh = (__half*)smem;
    __half* sAl = sAh + 128 * PADH;
    __half* sBh = sAl + 128 * PADH;
    __half* sBl = sBh + NCOLS * PADH;

    const int tid = threadIdx.x;
    const int lane = tid & 31;
    const int rw = (tid >> 5) & 3;
    const int cw = tid >> 7;
    const int g = lane >> 2, q = lane & 3;
    const int nch = (K1 + K2) >> 6;

    const uint32_t sb = smem_u32(smem);
    const uint32_t oAh = 0;
    const uint32_t oAl = 128 * PADH * 2;
    const uint32_t oBh = 2 * 128 * PADH * 2;
    const uint32_t oBl = oBh + NCOLS * PADH * 2;
    const int l15 = lane & 15, l16 = lane >> 4;
    const int b7 = lane & 7, bk8 = (lane >> 3) & 1;
    const uint32_t bsel = (lane >= 16) ? oBl : oBh;

    for (int tile = blockIdx.x; tile < ntiles; tile += gridDim.x) {
        float acc[2][NB][4];
#pragma unroll
        for (int mb = 0; mb < 2; mb++)
#pragma unroll
            for (int nb = 0; nb < NB; nb++)
#pragma unroll
                for (int j = 0; j < 4; j++) acc[mb][nb][j] = 0.0f;

        for (int ch = 0; ch < nch; ch++) {
            const int kb = ch << 6;
            const __half* Ah; const __half* Al; int lda, kloc;
            if (kb < K1) { Ah = Ah1; Al = Al1; lda = lda1; kloc = kb; }
            else         { Ah = Ah2; Al = Al2; lda = lda2; kloc = kb - K1; }

            __syncthreads();
            for (int u = tid; u < 1024; u += 256) {
                int row = u >> 3, k8 = (u & 7) << 3;
                int node = tile * 128 + row;
                uint4 vh = make_uint4(0, 0, 0, 0), vl = vh;
                if (node < n) {
                    vh = *(const uint4*)(Ah + (size_t)node * lda + kloc + k8);
                    vl = *(const uint4*)(Al + (size_t)node * lda + kloc + k8);
                }
                *(uint4*)(sAh + row * PADH + k8) = vh;
                *(uint4*)(sAl + row * PADH + k8) = vl;
            }
            for (int u = tid; u < NCOLS * 8; u += 256) {
                int nn = u >> 3, k8 = (u & 7) << 3;
                const __half* wrh;
                const __half* wrl;
                if (NCOLS == 64 || nn < 64) { wrh = Wh_a + (size_t)nn * Kw; wrl = Wl_a + (size_t)nn * Kw; }
                else { wrh = Wh_b + (size_t)(nn - 64) * Kw; wrl = Wl_b + (size_t)(nn - 64) * Kw; }
                *(uint4*)(sBh + nn * PADH + k8) = *(const uint4*)(wrh + kb + k8);
                *(uint4*)(sBl + nn * PADH + k8) = *(const uint4*)(wrl + kb + k8);
            }
            __syncthreads();

#pragma unroll
            for (int ks = 0; ks < 4; ks++) {
                uint32_t fah[2][4], fal[2][4];
#pragma unroll
                for (int mb = 0; mb < 2; mb++) {
                    uint32_t ao = (uint32_t)((rw * 32 + mb * 16 + l15) * PADH
                                             + ks * 16 + l16 * 8) * 2;
                    ldsm4(fah[mb], sb + oAh + ao);
                    ldsm4(fal[mb], sb + oAl + ao);
                }
#pragma unroll
                for (int nb = 0; nb < NB; nb++) {
                    uint32_t bo = (uint32_t)((cw * (NCOLS / 2) + nb * 8 + b7) * PADH
                                             + ks * 16 + bk8 * 8) * 2;
                    uint32_t bv[4];
                    ldsm4(bv, sb + bsel + bo);
#pragma unroll
                    for (int mb = 0; mb < 2; mb++) {
                        mma16816(acc[mb][nb], fah[mb], bv[0], bv[1]);
                        mma16816(acc[mb][nb], fah[mb], bv[2], bv[3]);
                        mma16816(acc[mb][nb], fal[mb], bv[0], bv[1]);
                    }
                }
            }
        }

        // epilogue
#pragma unroll
        for (int mb = 0; mb < 2; mb++) {
#pragma unroll
            for (int nb = 0; nb < NB; nb++) {
                int r0 = tile * 128 + rw * 32 + mb * 16 + g;
                int gc = cw * (NCOLS / 2) + nb * 8 + 2 * q;
                float* C; const float* bs; int ldc, col;
                __half* Ch = nullptr; __half* Cl = nullptr; int ldp = 0;
                if (NCOLS == 128 && gc >= 64) { C = C2; bs = bb; ldc = ldc2; col = gc - 64; }
                else { C = C1; bs = ba; ldc = ldc1; col = gc; Ch = C1h; Cl = C1l; ldp = ldc1p; }
                float b0 = bs ? bs[col] : 0.0f;
                float b1 = bs ? bs[col + 1] : 0.0f;
#pragma unroll
                for (int hh = 0; hh < 2; hh++) {
                    int r = r0 + hh * 8;
                    if (r >= n) continue;
                    float v0 = acc[mb][nb][2 * hh + 0] + b0;
                    float v1 = acc[mb][nb][2 * hh + 1] + b1;
                    if (RELU) { v0 = fmaxf(v0, 0.f); v1 = fmaxf(v1, 0.f); }
                    if (C) *(float2*)&C[(size_t)r * ldc + col] = make_float2(v0, v1);
                    if (Ch) {
                        __half h0, l0, h1, l1;
                        split_hl(v0, h0, l0);
                        split_hl(v1, h1, l1);
                        *(__half2*)&Ch[(size_t)r * ldp + col] = __halves2half2(h0, h1);
                        *(__half2*)&Cl[(size_t)r * ldp + col] = __halves2half2(l0, l1);
                    }
                }
            }
        }
    }
}

// ---------------- fp16 path gathers ----------------
// half in -> half out (optionally writes hi/lo pair out instead)
template<bool PAIROUT>
__global__ void k_gather_h(const int* __restrict__ off, const int* __restrict__ cnt,
                           const int* __restrict__ srcs,
                           const __half* __restrict__ A, int lda,
                           const float* __restrict__ sscale,
                           __half* __restrict__ out, __half* __restrict__ outl,
                           int n) {
    int gw = (blockIdx.x * blockDim.x + threadIdx.x) >> 5;
    int lane = threadIdx.x & 31;
    if (gw >= n) return;
    int start = off[gw];
    int num = cnt[gw];
    int c2 = lane * 2;
    float ax = 0.0f, ay = 0.0f;
    int i = 0;
    int n4 = num & ~3;
    for (; i < n4; i += 4) {
        int s0 = srcs[start + i + 0];
        int s1 = srcs[start + i + 1];
        int s2 = srcs[start + i + 2];
        int s3 = srcs[start + i + 3];
        float2 v0 = __half22float2(*(const __half2*)&A[(size_t)s0 * lda + c2]);
        float2 v1 = __half22float2(*(const __half2*)&A[(size_t)s1 * lda + c2]);
        float2 v2 = __half22float2(*(const __half2*)&A[(size_t)s2 * lda + c2]);
        float2 v3 = __half22float2(*(const __half2*)&A[(size_t)s3 * lda + c2]);
        float w0 = sscale[s0], w1 = sscale[s1], w2 = sscale[s2], w3 = sscale[s3];
        ax += v0.x * w0 + v1.x * w1 + v2.x * w2 + v3.x * w3;
        ay += v0.y * w0 + v1.y * w1 + v2.y * w2 + v3.y * w3;
    }
    for (; i < num; i++) {
        int s = srcs[start + i];
        float2 v = __half22float2(*(const __half2*)&A[(size_t)s * lda + c2]);
        float w = sscale[s];
        ax += v.x * w;
        ay += v.y * w;
    }
    if (PAIROUT) {
        __half h0, l0, h1, l1;
        split_hl(ax, h0, l0);
        split_hl(ay, h1, l1);
        *(__half2*)&out[(size_t)gw * 64 + c2]  = __halves2half2(h0, h1);
        *(__half2*)&outl[(size_t)gw * 64 + c2] = __halves2half2(l0, l1);
    } else {
        *(__half2*)&out[(size_t)gw * 64 + c2] = __float22half2_rn(make_float2(ax, ay));
    }
}

// ---------------- fused gather + SAGE epilogue (pairs out) ----------------
__global__ void k_gatherpost(const int* __restrict__ off, const int* __restrict__ cnt,
                             const int* __restrict__ srcs,
                             const float* __restrict__ A, int lda,
                             const float* __restrict__ R, int ldr,
                             const float* __restrict__ invin,
                             const float* __restrict__ bias,
                             const float* __restrict__ gam, const float* __restrict__ bet,
                             const float* __restrict__ mea, const float* __restrict__ var,
                             const __half* __restrict__ hh, const __half* __restrict__ hl,
                             int ldh,
                             __half* __restrict__ outh, __half* __restrict__ outl,
                             int ldo, int n) {
    int gw = (blockIdx.x * blockDim.x + threadIdx.x) >> 5;
    int lane = threadIdx.x & 31;
    if (gw >= n) return;
    int start = off[gw];
    int num = cnt[gw];
    int c0 = lane * 2, c1 = c0 + 1;
    float ax = 0.0f, ay = 0.0f;
    int i = 0;
    int n4 = num & ~3;
    for (; i < n4; i += 4) {
        int s0 = srcs[start + i + 0];
        int s1 = srcs[start + i + 1];
        int s2 = srcs[start + i + 2];
        int s3 = srcs[start + i + 3];
        float2 v0 = *(const float2*)&A[(size_t)s0 * lda + c0];
        float2 v1 = *(const float2*)&A[(size_t)s1 * lda + c0];
        float2 v2 = *(const float2*)&A[(size_t)s2 * lda + c0];
        float2 v3 = *(const float2*)&A[(size_t)s3 * lda + c0];
        ax += v0.x + v1.x + v2.x + v3.x;
        ay += v0.y + v1.y + v2.y + v3.y;
    }
    for (; i < num; i++) {
        int s = srcs[start + i];
        float2 v = *(const float2*)&A[(size_t)s * lda + c0];
        ax += v.x;
        ay += v.y;
    }
    float inv = invin[gw];
    float r0 = R[(size_t)gw * ldr + c0];
    float r1 = R[(size_t)gw * ldr + c1];
    float s0 = gam[c0] * rsqrtf(var[c0] + EPSV);
    float s1 = gam[c1] * rsqrtf(var[c1] + EPSV);
    float v0 = (ax * inv + bias[c0] + r0 - mea[c0]) * s0 + bet[c0];
    float v1 = (ay * inv + bias[c1] + r1 - mea[c1]) * s1 + bet[c1];
    v0 = fmaxf(v0, 0.0f);
    v1 = fmaxf(v1, 0.0f);
    if (hh) {
        float2 ph = __half22float2(*(const __half2*)&hh[(size_t)gw * ldh + c0]);
        float2 pl = __half22float2(*(const __half2*)&hl[(size_t)gw * ldh + c0]);
        v0 += ph.x + pl.x;
        v1 += ph.y + pl.y;
    }
    __half h0, l0, h1, l1;
    split_hl(v0, h0, l0);
    split_hl(v1, h1, l1);
    *(__half2*)&outh[(size_t)gw * ldo + c0] = __halves2half2(h0, h1);
    *(__half2*)&outl[(size_t)gw * ldo + c0] = __halves2half2(l0, l1);
}

// ---------------- rank head ----------------
__global__ void k_rankdot(const float* __restrict__ t, const float* __restrict__ W2,
                          const float* __restrict__ b2, float* __restrict__ out, int n) {
    int gw = (blockIdx.x * blockDim.x + threadIdx.x) >> 5;
    int lane = threadIdx.x & 31;
    if (gw >= n) return;
    int c = lane * 2;
    float2 tv = *(const float2*)&t[(size_t)gw * 64 + c];
    float s = tv.x * W2[c] + tv.y * W2[c + 1];
#pragma unroll
    for (int o = 16; o > 0; o >>= 1) s += __shfl_xor_sync(0xffffffffu, s, o);
    if (lane == 0) out[gw] = s + b2[0];
}

// ---------------- regressor tail ----------------
__global__ void k_regfinal(const float* __restrict__ pre, const float* __restrict__ w1last,
                           const float* __restrict__ b1, const float* __restrict__ score,
                           const float* __restrict__ W2, const float* __restrict__ b2,
                           const float* __restrict__ W3, const float* __restrict__ b3,
                           float* __restrict__ preds, int n) {
    __shared__ float h1s[8][66];
    int wmy = threadIdx.x >> 5;
    int lane = threadIdx.x & 31;
    int node = blockIdx.x * 8 + wmy;
    if (node >= n) return;
    float sc = score[node];
    int c = lane * 2;
    float a0 = pre[(size_t)node * 64 + c]     + sc * w1last[c]     + b1[c];
    float a1 = pre[(size_t)node * 64 + c + 1] + sc * w1last[c + 1] + b1[c + 1];
    h1s[wmy][c]     = fmaxf(a0, 0.0f);
    h1s[wmy][c + 1] = fmaxf(a1, 0.0f);
    __syncwarp();
    float h2 = b2[lane];
#pragma unroll 8
    for (int k = 0; k < 64; k++) h2 += h1s[wmy][k] * W2[k * 32 + lane];
    h2 = fmaxf(h2, 0.0f);
    float p = h2 * W3[lane];
#pragma unroll
    for (int o = 16; o > 0; o >>= 1) p += __shfl_xor_sync(0xffffffffu, p, o);
    if (lane == 0) preds[node] = p + b3[0];
}

// ---------------- host ----------------
static const int SMEM128 = (128 + 128) * PADH * 2 * 2;  // 73728
static const int SMEM64  = (128 + 64) * PADH * 2 * 2;   // 55296

static cudaStream_t g_s2 = nullptr;
static cudaEvent_t g_evA, g_evB, g_evC, g_evD;

extern "C" void kernel_launch(void* const* d_in, const int* in_sizes, int n_in,
                              void* d_out, int out_size) {
    const float* x        = (const float*)d_in[0];
    const int*   ei       = (const int*)d_in[1];
    const float* W_in     = (const float*)d_in[2];
    const float* b_in     = (const float*)d_in[3];
    const float* sage_Wl  = (const float*)d_in[4];
    const float* sage_bl  = (const float*)d_in[5];
    const float* sage_Wr  = (const float*)d_in[6];
    const float* bn_g     = (const float*)d_in[7];
    const float* bn_b     = (const float*)d_in[8];
    const float* bn_m     = (const float*)d_in[9];
    const float* bn_v     = (const float*)d_in[10];
    const float* vW_l     = (const float*)d_in[11];
    const float* vb_l     = (const float*)d_in[12];
    const float* vW_r     = (const float*)d_in[13];
    const float* vbn_g    = (const float*)d_in[14];
    const float* vbn_b    = (const float*)d_in[15];
    const float* vbn_m    = (const float*)d_in[16];
    const float* vbn_v    = (const float*)d_in[17];
    const float* W_mu     = (const float*)d_in[18];
    const float* b_mu     = (const float*)d_in[19];
    const float* W_lv     = (const float*)d_in[20];
    const float* b_lv     = (const float*)d_in[21];
    const float* rank_W1  = (const float*)d_in[22];
    const float* rank_b1  = (const float*)d_in[23];
    const float* rank_W2  = (const float*)d_in[24];
    const float* rank_b2  = (const float*)d_in[25];
    const float* reg_W1   = (const float*)d_in[26];
    const float* reg_b1   = (const float*)d_in[27];
    const float* reg_W2   = (const float*)d_in[28];
    const float* reg_b2   = (const float*)d_in[29];
    const float* reg_W3   = (const float*)d_in[30];
    const float* reg_b3   = (const float*)d_in[31];

    int n = in_sizes[0] / 64;
    int e = in_sizes[1] / 2;
    const int* rowv = ei;
    const int* colv = ei + e;

    if (!g_s2) {
        cudaStreamCreateWithFlags(&g_s2, cudaStreamNonBlocking);
        cudaEventCreateWithFlags(&g_evA, cudaEventDisableTiming);
        cudaEventCreateWithFlags(&g_evB, cudaEventDisableTiming);
        cudaEventCreateWithFlags(&g_evC, cudaEventDisableTiming);
        cudaEventCreateWithFlags(&g_evD, cudaEventDisableTiming);
        cudaFuncSetAttribute(k_mmagemm<128, false>, cudaFuncAttributeMaxDynamicSharedMemorySize, SMEM128);
        cudaFuncSetAttribute(k_mmagemm<64, false>,  cudaFuncAttributeMaxDynamicSharedMemorySize, SMEM64);
        cudaFuncSetAttribute(k_mmagemm<64, true>,   cudaFuncAttributeMaxDynamicSharedMemorySize, SMEM64);
    }

    float *pr, *bufA, *tbuf, *invin, *invout;
    __half *xh, *xl, *s1h, *s1l, *hA, *hB, *bh, *bl, *vh, *vl, *mh, *ml, *wh, *wl;
    int *indeg, *outdeg, *off, *cursor, *srcs, *bsum;
    cudaGetSymbolAddress((void**)&pr, g_pr);
    cudaGetSymbolAddress((void**)&bufA, g_bufA);
    cudaGetSymbolAddress((void**)&tbuf, g_t);
    cudaGetSymbolAddress((void**)&xh, g_xh);
    cudaGetSymbolAddress((void**)&xl, g_xl);
    cudaGetSymbolAddress((void**)&s1h, g_s1h);
    cudaGetSymbolAddress((void**)&s1l, g_s1l);
    cudaGetSymbolAddress((void**)&hA, g_hA);
    cudaGetSymbolAddress((void**)&hB, g_hB);
    cudaGetSymbolAddress((void**)&bh, g_bh);
    cudaGetSymbolAddress((void**)&bl, g_bl2);
    cudaGetSymbolAddress((void**)&vh, g_vh);
    cudaGetSymbolAddress((void**)&vl, g_vl);
    cudaGetSymbolAddress((void**)&mh, g_mh);
    cudaGetSymbolAddress((void**)&ml, g_ml);
    cudaGetSymbolAddress((void**)&wh, g_wh);
    cudaGetSymbolAddress((void**)&wl, g_wl);
    cudaGetSymbolAddress((void**)&invin, g_invin);
    cudaGetSymbolAddress((void**)&invout, g_invout);
    cudaGetSymbolAddress((void**)&indeg, g_indeg);
    cudaGetSymbolAddress((void**)&outdeg, g_outdeg);
    cudaGetSymbolAddress((void**)&off, g_off);
    cudaGetSymbolAddress((void**)&cursor, g_cursor);
    cudaGetSymbolAddress((void**)&srcs, g_srcs);
    cudaGetSymbolAddress((void**)&bsum, g_bsum);

    float* out_preds = (float*)d_out;
    float* out_rank  = out_preds + n;
    float* out_mu    = out_preds + 2 * (size_t)n;
    float* out_lv    = out_mu + 64 * (size_t)n;

    int ntiles = (n + 127) / 128;
    int gwb = (n * 32 + 255) / 256;
    int nb = (n + 1023) / 1024;

    // ---- fork: s2 does converters + inp_skip while s0 builds the graph ----
    cudaEventRecord(g_evA, 0);
    cudaStreamWaitEvent(g_s2, g_evA, 0);

    // s0: graph build
    cudaMemsetAsync(indeg, 0, n * sizeof(int), 0);
    cudaMemsetAsync(outdeg, 0, n * sizeof(int), 0);
    k_count<<<(e + 255) / 256, 256, 0, 0>>>(rowv, colv, indeg, outdeg, e);
    k_scan1<<<nb, 1024, 0, 0>>>(indeg, off, bsum, n);
    k_scan2<<<1, 32, 0, 0>>>(bsum, nb);
    k_scan3<<<nb, 1024, 0, 0>>>(off, bsum, cursor, indeg, outdeg, invin, invout, n);
    k_fill<<<(e + 255) / 256, 256, 0, 0>>>(rowv, colv, cursor, srcs, e);

    // s2: converters + inp_skip gemm (independent of graph)
    k_cvtx<<<(n * 64 + 255) / 256, 256, 0, g_s2>>>(x, xh, xl, n * 64);
    k_cvtw<<<(TOTW + 255) / 256, 256, 0, g_s2>>>(W_in, sage_Wl, sage_Wr, vW_l, vW_r,
                                                 W_mu, W_lv, rank_W1, reg_W1, wh, wl);
    k_mmagemm<64, false><<<ntiles, 256, SMEM64, g_s2>>>(
        xh, xl, 64, 64, nullptr, nullptr, 0, 0,
        wh + OFF_WIN, wl + OFF_WIN, nullptr, nullptr, 64,
        b_in, nullptr, nullptr, 0, nullptr, 0, s1h + 256, s1l + 256, 320, n, ntiles);
    cudaEventRecord(g_evB, g_s2);
    cudaStreamWaitEvent(0, g_evB, 0);

    // ---- 4 SAGE layers ----
    const __half* hhp = xh; const __half* hlp = xl;
    int lh = 64, hofs = 0;
    for (int i = 0; i < 4; i++) {
        k_mmagemm<128, false><<<ntiles, 256, SMEM128, 0>>>(
            hhp + hofs, hlp + hofs, lh, 64, nullptr, nullptr, 0, 0,
            wh + OFF_SWL + i * 4096, wl + OFF_SWL + i * 4096,
            wh + OFF_SWR + i * 4096, wl + OFF_SWR + i * 4096, 64,
            nullptr, nullptr, pr, 128, pr + 64, 128, nullptr, nullptr, 0, n, ntiles);
        k_gatherpost<<<gwb, 256, 0, 0>>>(off, indeg, srcs, pr, 128, pr + 64, 128, invin,
                                         sage_bl + i * 64, bn_g + i * 64, bn_b + i * 64,
                                         bn_m + i * 64, bn_v + i * 64,
                                         hhp + hofs, hlp + hofs, lh,
                                         s1h + i * 64, s1l + i * 64, 320, n);
        hhp = s1h; hlp = s1l; lh = 320; hofs = i * 64;
    }

    // ---- path_agg: 4 steps, fp16 intermediates ----
    k_gather_h<false><<<gwb, 256, 0, 0>>>(off, indeg, srcs, s1h + 192, 320, invout, hA, nullptr, n);
    k_gather_h<false><<<gwb, 256, 0, 0>>>(off, indeg, srcs, hA, 64, invout, hB, nullptr, n);
    k_gather_h<false><<<gwb, 256, 0, 0>>>(off, indeg, srcs, hB, 64, invout, hA, nullptr, n);
    k_gather_h<true><<<gwb, 256, 0, 0>>>(off, indeg, srcs, hA, 64, invout, bh, bl, n);

    // ---- VGAE sage: [s1|path] (K=320+64) @ [vW_l|vW_r] ----
    k_mmagemm<128, false><<<ntiles, 256, SMEM128, 0>>>(
        s1h, s1l, 320, 320, bh, bl, 64, 64,
        wh + OFF_VWL, wl + OFF_VWL, wh + OFF_VWR, wl + OFF_VWR, 384,
        nullptr, nullptr, pr, 128, pr + 64, 128, nullptr, nullptr, 0, n, ntiles);
    k_gatherpost<<<gwb, 256, 0, 0>>>(off, indeg, srcs, pr, 128, pr + 64, 128, invin,
                                     vb_l, vbn_g, vbn_b, vbn_m, vbn_v,
                                     nullptr, nullptr, 0, vh, vl, 64, n);

    // ---- heads: [W_mu|W_lv]; mu also as pairs ----
    k_mmagemm<128, false><<<ntiles, 256, SMEM128, 0>>>(
        vh, vl, 64, 64, nullptr, nullptr, 0, 0,
        wh + OFF_WMU, wl + OFF_WMU, wh + OFF_WLV, wl + OFF_WLV, 64,
        b_mu, b_lv, out_mu, 64, out_lv, 64, mh, ml, 64, n, ntiles);

    // ---- tail fork: reg-pre on s2, rank head on s0 ----
    cudaEventRecord(g_evC, 0);
    cudaStreamWaitEvent(g_s2, g_evC, 0);
    k_mmagemm<64, false><<<ntiles, 256, SMEM64, g_s2>>>(
        s1h, s1l, 320, 320, mh, ml, 64, 64,
        wh + OFF_REG, wl + OFF_REG, nullptr, nullptr, 384,
        nullptr, nullptr, bufA, 64, nullptr, 0, nullptr, nullptr, 0, n, ntiles);
    cudaEventRecord(g_evD, g_s2);

    k_mmagemm<64, true><<<ntiles, 256, SMEM64, 0>>>(
        mh, ml, 64, 64, nullptr, nullptr, 0, 0,
        wh + OFF_RNK, wl + OFF_RNK, nullptr, nullptr, 64,
        rank_b1, nullptr, tbuf, 64, nullptr, 0, nullptr, nullptr, 0, n, ntiles);
    k_rankdot<<<gwb, 256, 0, 0>>>(tbuf, rank_W2, rank_b2, out_rank, n);

    cudaStreamWaitEvent(0, g_evD, 0);
    k_regfinal<<<(n + 7) / 8, 256, 0, 0>>>(bufA, reg_W1 + 384 * 64, reg_b1, out_rank,
                                           reg_W2, reg_b2, reg_W3, reg_b3, out_preds, n);
}